// round 4
// baseline (speedup 1.0000x reference)
#include <cuda_runtime.h>
#include <cuda_bf16.h>
#include <cstdint>

// Problem constants
#define BATCH   2
#define S_LEN   2048
#define D_MODEL 768
#define N_HEADS 12
#define HEAD_D  64
#define M_ROWS  (BATCH * S_LEN)   // 4096

// ---------------------------------------------------------------------------
// Scratch (no allocations allowed -> __device__ globals)
// ---------------------------------------------------------------------------
__device__ float g_q[M_ROWS * D_MODEL];
__device__ float g_k[M_ROWS * D_MODEL];
__device__ float g_v[M_ROWS * D_MODEL];
__device__ float g_att[M_ROWS * D_MODEL];

// ---------------------------------------------------------------------------
// GEMM: C[M,N] = A[M,K] @ W[K,N] + bias   (all row-major, M=4096, N=K=768)
// 128x128 block tile, BK=8, 256 threads, 8x8 per-thread micro-tile.
// ---------------------------------------------------------------------------
__global__ __launch_bounds__(256)
void gemm_bias_kernel(const float* __restrict__ A,
                      const float* __restrict__ W,
                      const float* __restrict__ bias,
                      float* __restrict__ C,
                      int M, int N, int K) {
    __shared__ float As[8][132];   // k-major, padded (132) for conflict-free
    __shared__ float Ws[8][132];

    const int tid  = threadIdx.x;
    const int tx   = tid & 15;          // 0..15 -> N dir
    const int ty   = tid >> 4;          // 0..15 -> M dir
    const int row0 = blockIdx.y * 128;
    const int col0 = blockIdx.x * 128;

    // A tile loaders: 128 rows x 8 cols = 256 float4
    const int arow = tid >> 1;              // 0..127
    const int acol = (tid & 1) << 2;        // 0 or 4
    // W tile loaders: 8 rows x 128 cols = 256 float4
    const int wrow = tid >> 5;              // 0..7
    const int wcol = (tid & 31) << 2;       // 0..124

    const float* Ap = A + (size_t)(row0 + arow) * K + acol;
    const float* Wp = W + (size_t)wrow * N + col0 + wcol;

    float acc[8][8];
#pragma unroll
    for (int i = 0; i < 8; i++)
#pragma unroll
        for (int j = 0; j < 8; j++) acc[i][j] = 0.f;

    for (int k0 = 0; k0 < K; k0 += 8) {
        float4 a4 = *(const float4*)(Ap + k0);
        float4 w4 = *(const float4*)(Wp + (size_t)k0 * N);
        As[acol + 0][arow] = a4.x;
        As[acol + 1][arow] = a4.y;
        As[acol + 2][arow] = a4.z;
        As[acol + 3][arow] = a4.w;
        *(float4*)&Ws[wrow][wcol] = w4;
        __syncthreads();

#pragma unroll
        for (int kk = 0; kk < 8; kk++) {
            float af[8], wf[8];
            *(float4*)&af[0] = *(const float4*)&As[kk][ty * 8];
            *(float4*)&af[4] = *(const float4*)&As[kk][ty * 8 + 4];
            *(float4*)&wf[0] = *(const float4*)&Ws[kk][tx * 8];
            *(float4*)&wf[4] = *(const float4*)&Ws[kk][tx * 8 + 4];
#pragma unroll
            for (int i = 0; i < 8; i++)
#pragma unroll
                for (int j = 0; j < 8; j++)
                    acc[i][j] += af[i] * wf[j];
        }
        __syncthreads();
    }

    // Epilogue: += bias, vectorized stores
    float4 b0 = *(const float4*)(bias + col0 + tx * 8);
    float4 b1 = *(const float4*)(bias + col0 + tx * 8 + 4);
#pragma unroll
    for (int i = 0; i < 8; i++) {
        const size_t r = (size_t)(row0 + ty * 8 + i);
        float4 o0 = make_float4(acc[i][0] + b0.x, acc[i][1] + b0.y,
                                acc[i][2] + b0.z, acc[i][3] + b0.w);
        float4 o1 = make_float4(acc[i][4] + b1.x, acc[i][5] + b1.y,
                                acc[i][6] + b1.z, acc[i][7] + b1.w);
        *(float4*)(C + r * N + col0 + tx * 8)     = o0;
        *(float4*)(C + r * N + col0 + tx * 8 + 4) = o1;
    }
}

// ---------------------------------------------------------------------------
// Flash attention (fp32, no mask). Block = 64 q-rows, one (b, h).
// 256 threads as 16x16 grid; each thread owns a 4x4 tile of the 64x64
// score tile AND of the 64x64 output tile. K is stored d-major in smem
// (transposed at load) so both inner GEMMs read conflict-free float4s.
// ---------------------------------------------------------------------------
#define BQ   64
#define BKV  64
#define LDS_ 68          // 64 + 4 pad

__global__ __launch_bounds__(256)
void attn_kernel(const float* __restrict__ Q,
                 const float* __restrict__ K,
                 const float* __restrict__ V,
                 float* __restrict__ O) {
    extern __shared__ float sm[];
    float* Qs = sm;                      // [64][68]  q-major (row q, col d), pre-scaled
    float* KT = Qs + 64 * LDS_;          // [64][68]  d-major (row d, col kv)
    float* Vs = KT + 64 * LDS_;          // [64][68]  kv-major (row kv, col d)
    float* Ps = Vs + 64 * LDS_;          // [64][68]  score tile (row q, col kv)
    __shared__ float mrow[64], lrow[64], arow[64];

    const int tid = threadIdx.x;
    const int tx  = tid & 15;            // kv / head-dim direction
    const int ty  = tid >> 4;            // q direction
    const int b   = blockIdx.z;
    const int h   = blockIdx.y;
    const int q0  = blockIdx.x * BQ;

    const float* qb = Q + ((size_t)b * S_LEN + q0) * D_MODEL + h * HEAD_D;
    const float* kb = K + (size_t)b * S_LEN * D_MODEL + h * HEAD_D;
    const float* vb = V + (size_t)b * S_LEN * D_MODEL + h * HEAD_D;

    // Load Q tile (pre-scaled by 1/sqrt(Dh) = 0.125)
    for (int it = tid; it < 64 * 16; it += 256) {
        const int r = it >> 4, c = (it & 15) << 2;
        float4 t = *(const float4*)(qb + (size_t)r * D_MODEL + c);
        Qs[r * LDS_ + c + 0] = t.x * 0.125f;
        Qs[r * LDS_ + c + 1] = t.y * 0.125f;
        Qs[r * LDS_ + c + 2] = t.z * 0.125f;
        Qs[r * LDS_ + c + 3] = t.w * 0.125f;
    }
    if (tid < 64) { mrow[tid] = -1e30f; lrow[tid] = 0.f; }

    float acc[4][4];
#pragma unroll
    for (int i = 0; i < 4; i++)
#pragma unroll
        for (int j = 0; j < 4; j++) acc[i][j] = 0.f;

    __syncthreads();

    for (int kt = 0; kt < S_LEN; kt += BKV) {
        // --- K tile, transposed into KT[d][kv]; store pattern is conflict-free
        for (int it = tid; it < 64 * 16; it += 256) {
            const int kv = it & 63, dc = (it >> 6) << 2;
            float4 t = *(const float4*)(kb + (size_t)(kt + kv) * D_MODEL + dc);
            KT[(dc + 0) * LDS_ + kv] = t.x;
            KT[(dc + 1) * LDS_ + kv] = t.y;
            KT[(dc + 2) * LDS_ + kv] = t.z;
            KT[(dc + 3) * LDS_ + kv] = t.w;
        }
        // --- V tile, natural layout Vs[kv][d]
        for (int it = tid; it < 64 * 16; it += 256) {
            const int r = it >> 4, c = (it & 15) << 2;
            *(float4*)&Vs[r * LDS_ + c] =
                *(const float4*)(vb + (size_t)(kt + r) * D_MODEL + c);
        }
        __syncthreads();

        // --- P = Qs @ KT  (64x64x64), 4x4 per thread, d in float4 chunks
        float p[4][4];
#pragma unroll
        for (int i = 0; i < 4; i++)
#pragma unroll
            for (int j = 0; j < 4; j++) p[i][j] = 0.f;

#pragma unroll 4
        for (int d0 = 0; d0 < HEAD_D; d0 += 4) {
            float4 qv[4], kv4[4];
#pragma unroll
            for (int i = 0; i < 4; i++)
                qv[i] = *(const float4*)&Qs[(ty * 4 + i) * LDS_ + d0];
#pragma unroll
            for (int u = 0; u < 4; u++)
                kv4[u] = *(const float4*)&KT[(d0 + u) * LDS_ + tx * 4];
#pragma unroll
            for (int i = 0; i < 4; i++) {
                p[i][0] += qv[i].x * kv4[0].x; p[i][1] += qv[i].x * kv4[0].y;
                p[i][2] += qv[i].x * kv4[0].z; p[i][3] += qv[i].x * kv4[0].w;
                p[i][0] += qv[i].y * kv4[1].x; p[i][1] += qv[i].y * kv4[1].y;
                p[i][2] += qv[i].y * kv4[1].z; p[i][3] += qv[i].y * kv4[1].w;
                p[i][0] += qv[i].z * kv4[2].x; p[i][1] += qv[i].z * kv4[2].y;
                p[i][2] += qv[i].z * kv4[2].z; p[i][3] += qv[i].z * kv4[2].w;
                p[i][0] += qv[i].w * kv4[3].x; p[i][1] += qv[i].w * kv4[3].y;
                p[i][2] += qv[i].w * kv4[3].z; p[i][3] += qv[i].w * kv4[3].w;
            }
        }
#pragma unroll
        for (int i = 0; i < 4; i++)
            *(float4*)&Ps[(ty * 4 + i) * LDS_ + tx * 4] =
                make_float4(p[i][0], p[i][1], p[i][2], p[i][3]);
        __syncthreads();

        // --- Online softmax row stats (one thread per q-row)
        if (tid < 64) {
            const float mo = mrow[tid];
            float mx = mo;
            const float* pr = &Ps[tid * LDS_];
#pragma unroll 8
            for (int j = 0; j < 64; j++) mx = fmaxf(mx, pr[j]);
            const float al = __expf(mo - mx);
            mrow[tid] = mx;
            arow[tid] = al;
            lrow[tid] *= al;
        }
        __syncthreads();

        // --- Exponentiate (all 256 threads, 16 elems each) + row sums
        {
            const int r  = tid >> 2;
            const int c0 = (tid & 3) << 4;
            const float mx = mrow[r];
            float* pr = &Ps[r * LDS_ + c0];
            float s = 0.f;
#pragma unroll
            for (int j = 0; j < 16; j++) {
                const float e = __expf(pr[j] - mx);
                pr[j] = e;
                s += e;
            }
            s += __shfl_xor_sync(0xffffffffu, s, 1);
            s += __shfl_xor_sync(0xffffffffu, s, 2);
            if ((tid & 3) == 0) lrow[r] += s;
        }
        __syncthreads();

        // --- Rescale accumulators, then O += P @ V (64x64x64)
        float av[4];
#pragma unroll
        for (int i = 0; i < 4; i++) av[i] = arow[ty * 4 + i];
#pragma unroll
        for (int i = 0; i < 4; i++)
#pragma unroll
            for (int j = 0; j < 4; j++) acc[i][j] *= av[i];

#pragma unroll 4
        for (int d0 = 0; d0 < BKV; d0 += 4) {   // d0 = kv index
            float4 pv[4], vv[4];
#pragma unroll
            for (int i = 0; i < 4; i++)
                pv[i] = *(const float4*)&Ps[(ty * 4 + i) * LDS_ + d0];
#pragma unroll
            for (int u = 0; u < 4; u++)
                vv[u] = *(const float4*)&Vs[(d0 + u) * LDS_ + tx * 4];
#pragma unroll
            for (int i = 0; i < 4; i++) {
                acc[i][0] += pv[i].x * vv[0].x; acc[i][1] += pv[i].x * vv[0].y;
                acc[i][2] += pv[i].x * vv[0].z; acc[i][3] += pv[i].x * vv[0].w;
                acc[i][0] += pv[i].y * vv[1].x; acc[i][1] += pv[i].y * vv[1].y;
                acc[i][2] += pv[i].y * vv[1].z; acc[i][3] += pv[i].y * vv[1].w;
                acc[i][0] += pv[i].z * vv[2].x; acc[i][1] += pv[i].z * vv[2].y;
                acc[i][2] += pv[i].z * vv[2].z; acc[i][3] += pv[i].z * vv[2].w;
                acc[i][0] += pv[i].w * vv[3].x; acc[i][1] += pv[i].w * vv[3].y;
                acc[i][2] += pv[i].w * vv[3].z; acc[i][3] += pv[i].w * vv[3].w;
            }
        }
        __syncthreads();
    }

    // --- Epilogue: normalize by row sums, write [b, q, h*64 + d]
    float* ob = O + ((size_t)b * S_LEN + q0) * D_MODEL + h * HEAD_D;
#pragma unroll
    for (int i = 0; i < 4; i++) {
        const float li = 1.f / lrow[ty * 4 + i];
        float4 o = make_float4(acc[i][0] * li, acc[i][1] * li,
                               acc[i][2] * li, acc[i][3] * li);
        *(float4*)(ob + (size_t)(ty * 4 + i) * D_MODEL + tx * 4) = o;
    }
}

// ---------------------------------------------------------------------------
// Launch
// ---------------------------------------------------------------------------
extern "C" void kernel_launch(void* const* d_in, const int* in_sizes, int n_in,
                              void* d_out, int out_size) {
    const float* x  = (const float*)d_in[0];
    const float* Wq = (const float*)d_in[1];
    const float* bq = (const float*)d_in[2];
    const float* Wk = (const float*)d_in[3];
    const float* bk = (const float*)d_in[4];
    const float* Wv = (const float*)d_in[5];
    const float* bv = (const float*)d_in[6];
    const float* Wo = (const float*)d_in[7];
    const float* bo = (const float*)d_in[8];
    float* out = (float*)d_out;

    void *qp, *kp, *vp, *ap;
    cudaGetSymbolAddress(&qp, g_q);
    cudaGetSymbolAddress(&kp, g_k);
    cudaGetSymbolAddress(&vp, g_v);
    cudaGetSymbolAddress(&ap, g_att);

    const int ATT_SMEM = 4 * 64 * LDS_ * (int)sizeof(float);  // 69632 B
    cudaFuncSetAttribute(attn_kernel,
                         cudaFuncAttributeMaxDynamicSharedMemorySize, ATT_SMEM);

    dim3 gemm_grid(D_MODEL / 128, M_ROWS / 128);   // (6, 32)

    gemm_bias_kernel<<<gemm_grid, 256>>>(x, Wq, bq, (float*)qp,
                                         M_ROWS, D_MODEL, D_MODEL);
    gemm_bias_kernel<<<gemm_grid, 256>>>(x, Wk, bk, (float*)kp,
                                         M_ROWS, D_MODEL, D_MODEL);
    gemm_bias_kernel<<<gemm_grid, 256>>>(x, Wv, bv, (float*)vp,
                                         M_ROWS, D_MODEL, D_MODEL);

    dim3 attn_grid(S_LEN / BQ, N_HEADS, BATCH);    // (32, 12, 2)
    attn_kernel<<<attn_grid, 256, ATT_SMEM>>>((const float*)qp,
                                              (const float*)kp,
                                              (const float*)vp,
                                              (float*)ap);

    gemm_bias_kernel<<<gemm_grid, 256>>>((const float*)ap, Wo, bo, out,
                                         M_ROWS, D_MODEL, D_MODEL);
}

// round 7
// speedup vs baseline: 2.4953x; 2.4953x over previous
#include <cuda_runtime.h>
#include <cuda_bf16.h>
#include <cstdint>

// Problem constants
#define BATCH   2
#define S_LEN   2048
#define D_MODEL 768
#define N_HEADS 12
#define HEAD_D  64
#define M_ROWS  (BATCH * S_LEN)   // 4096

// ---------------------------------------------------------------------------
// Scratch (no allocations allowed -> __device__ globals)
// ---------------------------------------------------------------------------
__device__ float g_q[M_ROWS * D_MODEL];
__device__ float g_k[M_ROWS * D_MODEL];
__device__ float g_v[M_ROWS * D_MODEL];
__device__ float g_att[M_ROWS * D_MODEL];

// ---------------------------------------------------------------------------
// tf32 helpers
// ---------------------------------------------------------------------------
__device__ __forceinline__ unsigned f2tf(float x) {
    unsigned r;
    asm("cvt.rna.tf32.f32 %0, %1;" : "=r"(r) : "f"(x));
    return r;
}

// D = A(16x8, row) * B(8x8, col) + D, tf32 in, fp32 accumulate
__device__ __forceinline__ void mma8(float c[4], const unsigned a[4],
                                     const unsigned b[2]) {
    asm volatile(
        "mma.sync.aligned.m16n8k8.row.col.f32.tf32.tf32.f32 "
        "{%0,%1,%2,%3}, {%4,%5,%6,%7}, {%8,%9}, {%0,%1,%2,%3};"
        : "+f"(c[0]), "+f"(c[1]), "+f"(c[2]), "+f"(c[3])
        : "r"(a[0]), "r"(a[1]), "r"(a[2]), "r"(a[3]),
          "r"(b[0]), "r"(b[1]));
}

// ---------------------------------------------------------------------------
// GEMM body: C[4096,768] = A[4096,768] @ W[768,768] + bias.
// Block 128x128, BK=32, 8 warps (2x4), warp tile 64x32 (4x4 mma tiles).
// Smem pitches chosen so ALL fragment LDS are bank-conflict-free:
//   As pitch 36: bank = 4*row + col  (row 0..7, col 0..3 -> distinct)
//   Ws pitch 136: bank = 8*k + n     (k 0..3,  n 0..7   -> distinct)
// tf32 conversion happens once at smem fill time.
// ---------------------------------------------------------------------------
#define GAP 36
#define GWP 136

__device__ __forceinline__
void gemm_body(const float* __restrict__ A, const float* __restrict__ W,
               const float* __restrict__ bias, float* __restrict__ C) {
    __shared__ unsigned As[128 * GAP];
    __shared__ unsigned Ws[32 * GWP];

    const int tid  = threadIdx.x;
    const int lane = tid & 31, wid = tid >> 5;
    const int g4   = lane >> 2, t4 = lane & 3;
    const int wm   = (wid >> 2) * 64;     // warp row offset (0 / 64)
    const int wn   = (wid & 3) * 32;      // warp col offset (0..96)
    const int row0 = blockIdx.y * 128;
    const int col0 = blockIdx.x * 128;

    // loaders
    const int ar = tid >> 3, ac = (tid & 7) << 2;   // A: 32 rows/iter x 32 cols
    const int wr = tid >> 5, wc = (tid & 31) << 2;  // W: 8 rows/iter x 128 cols

    float acc[4][4][4];
#pragma unroll
    for (int mi = 0; mi < 4; mi++)
#pragma unroll
        for (int ni = 0; ni < 4; ni++)
#pragma unroll
            for (int j = 0; j < 4; j++) acc[mi][ni][j] = 0.f;

    for (int k0 = 0; k0 < D_MODEL; k0 += 32) {
#pragma unroll
        for (int i = 0; i < 4; i++) {
            const int r = ar + i * 32;
            float4 v = *(const float4*)(A + (size_t)(row0 + r) * D_MODEL + k0 + ac);
            unsigned* p = &As[r * GAP + ac];
            p[0] = f2tf(v.x); p[1] = f2tf(v.y); p[2] = f2tf(v.z); p[3] = f2tf(v.w);
        }
#pragma unroll
        for (int i = 0; i < 4; i++) {
            const int r = wr + i * 8;
            float4 v = *(const float4*)(W + (size_t)(k0 + r) * D_MODEL + col0 + wc);
            unsigned* p = &Ws[r * GWP + wc];
            p[0] = f2tf(v.x); p[1] = f2tf(v.y); p[2] = f2tf(v.z); p[3] = f2tf(v.w);
        }
        __syncthreads();

#pragma unroll
        for (int kk = 0; kk < 32; kk += 8) {
            unsigned af[4][4], bf[4][2];
#pragma unroll
            for (int mi = 0; mi < 4; mi++) {
                const int r = wm + mi * 16 + g4;
                af[mi][0] = As[r * GAP + kk + t4];
                af[mi][1] = As[(r + 8) * GAP + kk + t4];
                af[mi][2] = As[r * GAP + kk + t4 + 4];
                af[mi][3] = As[(r + 8) * GAP + kk + t4 + 4];
            }
#pragma unroll
            for (int ni = 0; ni < 4; ni++) {
                const int c = wn + ni * 8 + g4;
                bf[ni][0] = Ws[(kk + t4) * GWP + c];
                bf[ni][1] = Ws[(kk + t4 + 4) * GWP + c];
            }
#pragma unroll
            for (int mi = 0; mi < 4; mi++)
#pragma unroll
                for (int ni = 0; ni < 4; ni++)
                    mma8(acc[mi][ni], af[mi], bf[ni]);
        }
        __syncthreads();
    }

    // epilogue: bias + store (float2 per fragment half)
#pragma unroll
    for (int mi = 0; mi < 4; mi++) {
        const int r = row0 + wm + mi * 16 + g4;
#pragma unroll
        for (int ni = 0; ni < 4; ni++) {
            const int c = col0 + wn + ni * 8 + t4 * 2;
            const float b0 = bias[c], b1 = bias[c + 1];
            *(float2*)(C + (size_t)r * D_MODEL + c) =
                make_float2(acc[mi][ni][0] + b0, acc[mi][ni][1] + b1);
            *(float2*)(C + (size_t)(r + 8) * D_MODEL + c) =
                make_float2(acc[mi][ni][2] + b0, acc[mi][ni][3] + b1);
        }
    }
}

// Fused QKV projection: z dim selects which of the three GEMMs (576 blocks
// in one launch -> better wave packing than 3x192).
__global__ __launch_bounds__(256)
void qkv_gemm(const float* __restrict__ x,
              const float* __restrict__ Wq, const float* __restrict__ bq,
              const float* __restrict__ Wk, const float* __restrict__ bk,
              const float* __restrict__ Wv, const float* __restrict__ bv,
              float* __restrict__ q, float* __restrict__ k,
              float* __restrict__ v) {
    const float *W, *bias;
    float* C;
    if (blockIdx.z == 0)      { W = Wq; bias = bq; C = q; }
    else if (blockIdx.z == 1) { W = Wk; bias = bk; C = k; }
    else                      { W = Wv; bias = bv; C = v; }
    gemm_body(x, W, bias, C);
}

__global__ __launch_bounds__(256)
void o_gemm(const float* __restrict__ A, const float* __restrict__ W,
            const float* __restrict__ bias, float* __restrict__ C) {
    gemm_body(A, W, bias, C);
}

// ---------------------------------------------------------------------------
// Flash attention with tf32 mma. Block = 64 q-rows, one (b,h). 8 warps as
// 4(m) x 2(n); warp tile 16x32 for both the 64x64 score tile and the 64x64
// output tile. Smem pitches: Qs/Ps 68 (bank = 4r+c for A-frags), KT/Vs 72
// (bank = 8k+c for B-frags) -> all fragment LDS conflict-free.
// ---------------------------------------------------------------------------
#define AP 68
#define BP 72

__global__ __launch_bounds__(256)
void attn_tf32(const float* __restrict__ Q, const float* __restrict__ K,
               const float* __restrict__ V, float* __restrict__ O) {
    extern __shared__ unsigned sm_u[];
    unsigned* Qs = sm_u;                  // [64][68] tf32, pre-scaled q
    unsigned* KT = Qs + 64 * AP;          // [64][72] tf32, [d][kv]
    unsigned* Vs = KT + 64 * BP;          // [64][72] tf32, [kv][d]
    float*    Ps = (float*)(Vs + 64 * BP);// [64][68] fp32 score tile
    __shared__ float mrow[64], lrow[64], arow[64];

    const int tid  = threadIdx.x;
    const int lane = tid & 31, wid = tid >> 5;
    const int g4   = lane >> 2, t4 = lane & 3;
    const int wm   = (wid >> 1) * 16;     // warp q-row offset
    const int wn   = (wid & 1) * 32;      // warp col offset (kv / head-dim)
    const int b    = blockIdx.z, h = blockIdx.y;
    const int q0   = blockIdx.x * 64;

    const float* qb = Q + ((size_t)b * S_LEN + q0) * D_MODEL + h * HEAD_D;
    const float* kb = K + (size_t)b * S_LEN * D_MODEL + h * HEAD_D;
    const float* vb = V + (size_t)b * S_LEN * D_MODEL + h * HEAD_D;

    // Q tile: pre-scale by 1/sqrt(64)=0.125, convert to tf32
    for (int it = tid; it < 1024; it += 256) {
        const int r = it >> 4, c = (it & 15) << 2;
        float4 t = *(const float4*)(qb + (size_t)r * D_MODEL + c);
        unsigned* p = &Qs[r * AP + c];
        p[0] = f2tf(t.x * 0.125f); p[1] = f2tf(t.y * 0.125f);
        p[2] = f2tf(t.z * 0.125f); p[3] = f2tf(t.w * 0.125f);
    }
    if (tid < 64) { mrow[tid] = -1e30f; lrow[tid] = 0.f; }

    float oa[4][4];
#pragma unroll
    for (int ni = 0; ni < 4; ni++)
#pragma unroll
        for (int j = 0; j < 4; j++) oa[ni][j] = 0.f;

    __syncthreads();

    for (int kt = 0; kt < S_LEN; kt += 64) {
        // K tile transposed to [d][kv] (conflict-free scalar stores)
        for (int it = tid; it < 1024; it += 256) {
            const int kv = it & 63, dc = (it >> 6) << 2;
            float4 t = *(const float4*)(kb + (size_t)(kt + kv) * D_MODEL + dc);
            KT[(dc + 0) * BP + kv] = f2tf(t.x);
            KT[(dc + 1) * BP + kv] = f2tf(t.y);
            KT[(dc + 2) * BP + kv] = f2tf(t.z);
            KT[(dc + 3) * BP + kv] = f2tf(t.w);
        }
        // V tile natural [kv][d]
        for (int it = tid; it < 1024; it += 256) {
            const int r = it >> 4, c = (it & 15) << 2;
            float4 t = *(const float4*)(vb + (size_t)(kt + r) * D_MODEL + c);
            unsigned* p = &Vs[r * BP + c];
            p[0] = f2tf(t.x); p[1] = f2tf(t.y); p[2] = f2tf(t.z); p[3] = f2tf(t.w);
        }
        __syncthreads();

        // --- S = Q @ K^T on tensor pipe (k = 64 -> 8 mma k-steps)
        float sf[4][4];
#pragma unroll
        for (int ni = 0; ni < 4; ni++)
#pragma unroll
            for (int j = 0; j < 4; j++) sf[ni][j] = 0.f;

#pragma unroll
        for (int kk = 0; kk < HEAD_D; kk += 8) {
            unsigned af[4];
            af[0] = Qs[(wm + g4) * AP + kk + t4];
            af[1] = Qs[(wm + g4 + 8) * AP + kk + t4];
            af[2] = Qs[(wm + g4) * AP + kk + t4 + 4];
            af[3] = Qs[(wm + g4 + 8) * AP + kk + t4 + 4];
#pragma unroll
            for (int ni = 0; ni < 4; ni++) {
                unsigned bf[2];
                const int c = wn + ni * 8 + g4;
                bf[0] = KT[(kk + t4) * BP + c];
                bf[1] = KT[(kk + t4 + 4) * BP + c];
                mma8(sf[ni], af, bf);
            }
        }
#pragma unroll
        for (int ni = 0; ni < 4; ni++) {
            const int c = wn + ni * 8 + t4 * 2;
            *(float2*)&Ps[(wm + g4) * AP + c] =
                make_float2(sf[ni][0], sf[ni][1]);
            *(float2*)&Ps[(wm + g4 + 8) * AP + c] =
                make_float2(sf[ni][2], sf[ni][3]);
        }
        __syncthreads();

        // --- online softmax row stats
        if (tid < 64) {
            const float mo = mrow[tid];
            float mx = mo;
            const float* pr = &Ps[tid * AP];
#pragma unroll 8
            for (int j = 0; j < 64; j++) mx = fmaxf(mx, pr[j]);
            const float al = __expf(mo - mx);
            mrow[tid] = mx;
            arow[tid] = al;
            lrow[tid] *= al;
        }
        __syncthreads();

        // --- exponentiate (256 threads, 16 each) + row sums
        {
            const int r = tid >> 2;
            const int c0 = (tid & 3) << 4;
            const float mx = mrow[r];
            float* pr = &Ps[r * AP + c0];
            float s = 0.f;
#pragma unroll
            for (int j = 0; j < 16; j++) {
                const float e = __expf(pr[j] - mx);
                pr[j] = e;
                s += e;
            }
            s += __shfl_xor_sync(0xffffffffu, s, 1);
            s += __shfl_xor_sync(0xffffffffu, s, 2);
            if ((tid & 3) == 0) lrow[r] += s;
        }
        __syncthreads();

        // --- rescale accumulators, then O += P @ V on tensor pipe
        const float a0 = arow[wm + g4], a1 = arow[wm + g4 + 8];
#pragma unroll
        for (int ni = 0; ni < 4; ni++) {
            oa[ni][0] *= a0; oa[ni][1] *= a0;
            oa[ni][2] *= a1; oa[ni][3] *= a1;
        }
#pragma unroll
        for (int kk = 0; kk < 64; kk += 8) {
            unsigned af[4];
            af[0] = f2tf(Ps[(wm + g4) * AP + kk + t4]);
            af[1] = f2tf(Ps[(wm + g4 + 8) * AP + kk + t4]);
            af[2] = f2tf(Ps[(wm + g4) * AP + kk + t4 + 4]);
            af[3] = f2tf(Ps[(wm + g4 + 8) * AP + kk + t4 + 4]);
#pragma unroll
            for (int ni = 0; ni < 4; ni++) {
                unsigned bf[2];
                const int c = wn + ni * 8 + g4;
                bf[0] = Vs[(kk + t4) * BP + c];
                bf[1] = Vs[(kk + t4 + 4) * BP + c];
                mma8(oa[ni], af, bf);
            }
        }
        __syncthreads();
    }

    // --- epilogue: normalize, write [b, q, h*64 + d]
    float* ob = O + ((size_t)b * S_LEN + q0) * D_MODEL + h * HEAD_D;
    const float li0 = 1.f / lrow[wm + g4];
    const float li1 = 1.f / lrow[wm + g4 + 8];
#pragma unroll
    for (int ni = 0; ni < 4; ni++) {
        const int c = wn + ni * 8 + t4 * 2;
        *(float2*)(ob + (size_t)(wm + g4) * D_MODEL + c) =
            make_float2(oa[ni][0] * li0, oa[ni][1] * li0);
        *(float2*)(ob + (size_t)(wm + g4 + 8) * D_MODEL + c) =
            make_float2(oa[ni][2] * li1, oa[ni][3] * li1);
    }
}

// ---------------------------------------------------------------------------
// Launch
// ---------------------------------------------------------------------------
extern "C" void kernel_launch(void* const* d_in, const int* in_sizes, int n_in,
                              void* d_out, int out_size) {
    const float* x  = (const float*)d_in[0];
    const float* Wq = (const float*)d_in[1];
    const float* bq = (const float*)d_in[2];
    const float* Wk = (const float*)d_in[3];
    const float* bk = (const float*)d_in[4];
    const float* Wv = (const float*)d_in[5];
    const float* bv = (const float*)d_in[6];
    const float* Wo = (const float*)d_in[7];
    const float* bo = (const float*)d_in[8];
    float* out = (float*)d_out;

    void *qp, *kp, *vp, *ap;
    cudaGetSymbolAddress(&qp, g_q);
    cudaGetSymbolAddress(&kp, g_k);
    cudaGetSymbolAddress(&vp, g_v);
    cudaGetSymbolAddress(&ap, g_att);

    const int ATT_SMEM = (64 * AP + 64 * BP + 64 * BP + 64 * AP) * (int)sizeof(float);
    cudaFuncSetAttribute(attn_tf32,
                         cudaFuncAttributeMaxDynamicSharedMemorySize, ATT_SMEM);

    dim3 qkv_grid(D_MODEL / 128, M_ROWS / 128, 3);   // (6, 32, 3)
    qkv_gemm<<<qkv_grid, 256>>>(x, Wq, bq, Wk, bk, Wv, bv,
                                (float*)qp, (float*)kp, (float*)vp);

    dim3 attn_grid(S_LEN / 64, N_HEADS, BATCH);      // (32, 12, 2)
    attn_tf32<<<attn_grid, 256, ATT_SMEM>>>((const float*)qp,
                                            (const float*)kp,
                                            (const float*)vp,
                                            (float*)ap);

    dim3 o_grid(D_MODEL / 128, M_ROWS / 128);        // (6, 32)
    o_gemm<<<o_grid, 256>>>((const float*)ap, Wo, bo, out);
}

// round 9
// speedup vs baseline: 4.6246x; 1.8533x over previous
#include <cuda_runtime.h>
#include <cuda_fp16.h>
#include <cstdint>

// Problem constants
#define BATCH   2
#define S_LEN   2048
#define D_MODEL 768
#define N_HEADS 12
#define HEAD_D  64
#define M_ROWS  (BATCH * S_LEN)   // 4096

// ---------------------------------------------------------------------------
// Scratch (no allocations allowed -> __device__ globals). fp16 intermediates.
// ---------------------------------------------------------------------------
__device__ __half g_q[M_ROWS * D_MODEL];
__device__ __half g_k[M_ROWS * D_MODEL];
__device__ __half g_v[M_ROWS * D_MODEL];
__device__ __half g_att[M_ROWS * D_MODEL];

// ---------------------------------------------------------------------------
// mma / ldmatrix helpers
// ---------------------------------------------------------------------------
__device__ __forceinline__ void mma16(float c[4], const unsigned a[4],
                                      const unsigned b[2]) {
    asm volatile(
        "mma.sync.aligned.m16n8k16.row.col.f32.f16.f16.f32 "
        "{%0,%1,%2,%3}, {%4,%5,%6,%7}, {%8,%9}, {%0,%1,%2,%3};"
        : "+f"(c[0]), "+f"(c[1]), "+f"(c[2]), "+f"(c[3])
        : "r"(a[0]), "r"(a[1]), "r"(a[2]), "r"(a[3]),
          "r"(b[0]), "r"(b[1]));
}

__device__ __forceinline__ void ldsm_x4(unsigned& r0, unsigned& r1,
                                        unsigned& r2, unsigned& r3,
                                        const __half* p) {
    uint32_t a = (uint32_t)__cvta_generic_to_shared(p);
    asm volatile("ldmatrix.sync.aligned.m8n8.x4.shared.b16 {%0,%1,%2,%3}, [%4];"
                 : "=r"(r0), "=r"(r1), "=r"(r2), "=r"(r3) : "r"(a));
}

__device__ __forceinline__ void ldsm_x4t(unsigned& r0, unsigned& r1,
                                         unsigned& r2, unsigned& r3,
                                         const __half* p) {
    uint32_t a = (uint32_t)__cvta_generic_to_shared(p);
    asm volatile("ldmatrix.sync.aligned.m8n8.x4.trans.shared.b16 {%0,%1,%2,%3}, [%4];"
                 : "=r"(r0), "=r"(r1), "=r"(r2), "=r"(r3) : "r"(a));
}

// copy 4 contiguous elements gmem -> smem half (with conversion if needed)
__device__ __forceinline__ void cp4(__half* dst, const float* src) {
    float4 v = *(const float4*)src;
    *(__half2*)dst       = __floats2half2_rn(v.x, v.y);
    *(__half2*)(dst + 2) = __floats2half2_rn(v.z, v.w);
}
__device__ __forceinline__ void cp4(__half* dst, const __half* src) {
    *(uint2*)dst = *(const uint2*)src;
}
// store a float pair to float or half output
__device__ __forceinline__ void st2(float* p, float a, float b) {
    *(float2*)p = make_float2(a, b);
}
__device__ __forceinline__ void st2(__half* p, float a, float b) {
    *(__half2*)p = __floats2half2_rn(a, b);
}

// ---------------------------------------------------------------------------
// GEMM: C[4096,768] = A[4096,768] @ W[768,768] + bias.
// Block 128x128, BK=32 (24 k-tiles), 8 warps (2x4), warp tile 64x32,
// fp16 mma m16n8k16.
// As: [row][k] pitch 40 halves; Ws: natural [k][n] pitch 136 halves,
// B fragments via ldmatrix.trans. Double-buffered, one sync per k-tile.
// ---------------------------------------------------------------------------
#define AP_G 40
#define WP_G 136
#define KTILES (D_MODEL / 32)   // 24

template <typename TIN, typename TOUT>
__device__ __forceinline__
void gemm_body(const TIN* __restrict__ A, const float* __restrict__ W,
               const float* __restrict__ bias, TOUT* __restrict__ C) {
    __shared__ __half As[2][128 * AP_G];
    __shared__ __half Ws[2][32 * WP_G];

    const int tid  = threadIdx.x;
    const int lane = tid & 31, wid = tid >> 5;
    const int gid  = lane >> 2, tig = lane & 3;
    const int wm   = (wid >> 2) * 64;
    const int wn   = (wid & 3) * 32;
    const int row0 = blockIdx.y * 128;
    const int col0 = blockIdx.x * 128;

    float acc[4][4][4];
#pragma unroll
    for (int mi = 0; mi < 4; mi++)
#pragma unroll
        for (int ni = 0; ni < 4; ni++)
#pragma unroll
            for (int j = 0; j < 4; j++) acc[mi][ni][j] = 0.f;

    const int arow = tid >> 1, akc = (tid & 1) * 16;   // A fill geometry
    const int wkr  = tid >> 3, wnc = (tid & 7) * 16;   // W fill geometry

    // NOTE: macro arg k0 is fully parenthesized and no loop variable inside
    // the macro shadows any call-site variable (loop var is j only).
#define FILL_TILE(bf, k0)                                                      \
    {                                                                          \
        _Pragma("unroll")                                                      \
        for (int j = 0; j < 4; j++)                                            \
            cp4(&As[bf][arow * AP_G + akc + 4 * j],                            \
                A + (size_t)(row0 + arow) * D_MODEL + (k0) + akc + 4 * j);     \
        _Pragma("unroll")                                                      \
        for (int j = 0; j < 4; j++)                                            \
            cp4(&Ws[bf][wkr * WP_G + wnc + 4 * j],                             \
                W + (size_t)((k0) + wkr) * D_MODEL + col0 + wnc + 4 * j);      \
    }

    FILL_TILE(0, 0);
    __syncthreads();

    for (int t = 0; t < KTILES; t++) {
        const int buf = t & 1;
#pragma unroll
        for (int ks = 0; ks < 2; ks++) {
            const int kk = ks * 16;
            unsigned a[4][4];
#pragma unroll
            for (int mi = 0; mi < 4; mi++)
                ldsm_x4(a[mi][0], a[mi][1], a[mi][2], a[mi][3],
                        &As[buf][(wm + mi * 16 + (lane & 15)) * AP_G +
                                 kk + (lane >> 4) * 8]);
#pragma unroll
            for (int nip = 0; nip < 2; nip++) {
                unsigned r0, r1, r2, r3;
                ldsm_x4t(r0, r1, r2, r3,
                         &Ws[buf][(kk + (lane & 15)) * WP_G +
                                  wn + nip * 16 + (lane >> 4) * 8]);
                unsigned b0[2] = {r0, r1}, b1[2] = {r2, r3};
#pragma unroll
                for (int mi = 0; mi < 4; mi++) {
                    mma16(acc[mi][2 * nip],     a[mi], b0);
                    mma16(acc[mi][2 * nip + 1], a[mi], b1);
                }
            }
        }
        if (t < KTILES - 1) FILL_TILE(buf ^ 1, (t + 1) * 32);
        __syncthreads();
    }
#undef FILL_TILE

    // epilogue: bias + paired stores
#pragma unroll
    for (int mi = 0; mi < 4; mi++) {
        const int r = row0 + wm + mi * 16 + gid;
#pragma unroll
        for (int ni = 0; ni < 4; ni++) {
            const int c = col0 + wn + 8 * ni + 2 * tig;
            const float b0 = bias[c], b1 = bias[c + 1];
            st2(C + (size_t)r * D_MODEL + c,
                acc[mi][ni][0] + b0, acc[mi][ni][1] + b1);
            st2(C + (size_t)(r + 8) * D_MODEL + c,
                acc[mi][ni][2] + b0, acc[mi][ni][3] + b1);
        }
    }
}

__global__ __launch_bounds__(256)
void qkv_gemm(const float* __restrict__ x,
              const float* __restrict__ Wq, const float* __restrict__ bq,
              const float* __restrict__ Wk, const float* __restrict__ bk,
              const float* __restrict__ Wv, const float* __restrict__ bv,
              __half* __restrict__ q, __half* __restrict__ k,
              __half* __restrict__ v) {
    const float *W, *bias;
    __half* C;
    if (blockIdx.z == 0)      { W = Wq; bias = bq; C = q; }
    else if (blockIdx.z == 1) { W = Wk; bias = bk; C = k; }
    else                      { W = Wv; bias = bv; C = v; }
    gemm_body<float, __half>(x, W, bias, C);
}

__global__ __launch_bounds__(256)
void o_gemm(const __half* __restrict__ A, const float* __restrict__ W,
            const float* __restrict__ bias, float* __restrict__ C) {
    gemm_body<__half, float>(A, W, bias, C);
}

// ---------------------------------------------------------------------------
// Flash attention, fp16 mma, register-resident softmax.
// Block = 128 q-rows x one (b,h); 8 warps, each owns 16 q-rows x all 64 kv.
// Q in smem [128][72]; K,V natural [kv][d] [64][72], double-buffered.
// S-mma: A = Q (ldmatrix), B = K (ldmatrix non-trans: storage is [n][k]).
// PV-mma: A = P (registers, C-fragment == A-fragment identity),
//         B = V (ldmatrix.trans: storage is [k][n]).
// One __syncthreads per kv-tile.
// ---------------------------------------------------------------------------
#define QP 72
#define KP 72

__global__ __launch_bounds__(256)
void attn_f16(const __half* __restrict__ Q, const __half* __restrict__ K,
              const __half* __restrict__ V, __half* __restrict__ O) {
    extern __shared__ __half sh[];
    __half* Qs = sh;                   // [128][QP]
    __half* Ks = Qs + 128 * QP;        // [2][64*KP]
    __half* Vs = Ks + 2 * 64 * KP;     // [2][64*KP]

    const int tid  = threadIdx.x;
    const int lane = tid & 31, wid = tid >> 5;
    const int gid  = lane >> 2, tig = lane & 3;
    const int wm   = wid * 16;
    const int b    = blockIdx.z, h = blockIdx.y;
    const int q0   = blockIdx.x * 128;

    const __half* qb = Q + ((size_t)(b * S_LEN + q0)) * D_MODEL + h * HEAD_D;
    const __half* kb = K + ((size_t)b * S_LEN) * D_MODEL + h * HEAD_D;
    const __half* vb = V + ((size_t)b * S_LEN) * D_MODEL + h * HEAD_D;

    // Q fill, pre-scaled by 1/sqrt(64)=0.125 (exact power of two in fp16)
    const __half2 sc = __float2half2_rn(0.125f);
    for (int ii = tid; ii < 128 * 16; ii += 256) {
        const int r = ii >> 4, c4 = (ii & 15) * 4;
        uint2 u = *(const uint2*)(qb + (size_t)r * D_MODEL + c4);
        __half2 h0 = __hmul2(*(__half2*)&u.x, sc);
        __half2 h1 = __hmul2(*(__half2*)&u.y, sc);
        __half* d = &Qs[r * QP + c4];
        *(__half2*)d = h0;
        *(__half2*)(d + 2) = h1;
    }

    // NOTE: loop variable `ii` deliberately distinct from every call-site
    // variable (the R8 crash was `it` shadowing inside this macro, which made
    // the kt argument expand against the inner counter -> OOB global reads).
#define FILL_KV(bf, kt)                                                        \
    {                                                                          \
        __half* kd = &Ks[(bf) * 64 * KP];                                      \
        __half* vd = &Vs[(bf) * 64 * KP];                                      \
        for (int ii = tid; ii < 64 * 16; ii += 256) {                          \
            const int r = ii >> 4, c4 = (ii & 15) * 4;                         \
            *(uint2*)(&kd[r * KP + c4]) =                                      \
                *(const uint2*)(kb + (size_t)((kt) + r) * D_MODEL + c4);       \
            *(uint2*)(&vd[r * KP + c4]) =                                      \
                *(const uint2*)(vb + (size_t)((kt) + r) * D_MODEL + c4);       \
        }                                                                      \
    }

    float m0 = -1e30f, m1 = -1e30f, l0 = 0.f, l1 = 0.f;
    float oa[8][4];
#pragma unroll
    for (int ni = 0; ni < 8; ni++)
#pragma unroll
        for (int j = 0; j < 4; j++) oa[ni][j] = 0.f;

    FILL_KV(0, 0);
    __syncthreads();

    for (int t = 0; t < S_LEN / 64; ++t) {
        const int buf = t & 1;
        const __half* kbuf = &Ks[buf * 64 * KP];
        const __half* vbuf = &Vs[buf * 64 * KP];

        // --- S = Q @ K^T : rows wm..wm+15, all 64 kv cols, accum fp32
        float sf[8][4];
#pragma unroll
        for (int ni = 0; ni < 8; ni++)
#pragma unroll
            for (int j = 0; j < 4; j++) sf[ni][j] = 0.f;

#pragma unroll
        for (int s = 0; s < 4; s++) {          // k (head-dim) step of 16
            unsigned a[4];
            ldsm_x4(a[0], a[1], a[2], a[3],
                    &Qs[(wm + (lane & 15)) * QP + 16 * s + (lane >> 4) * 8]);
#pragma unroll
            for (int nip = 0; nip < 4; nip++) { // kv-tiles 2nip, 2nip+1
                unsigned r0, r1, r2, r3;
                ldsm_x4(r0, r1, r2, r3,
                        &kbuf[(nip * 16 + (lane & 7) + ((lane >> 4) & 1) * 8) * KP +
                              16 * s + ((lane >> 3) & 1) * 8]);
                unsigned bb0[2] = {r0, r1}, bb1[2] = {r2, r3};
                mma16(sf[2 * nip],     a, bb0);
                mma16(sf[2 * nip + 1], a, bb1);
            }
        }

        // --- register-resident online softmax (rows gid and gid+8)
        float mx0 = sf[0][0], mx1 = sf[0][2];
#pragma unroll
        for (int ni = 0; ni < 8; ni++) {
            mx0 = fmaxf(mx0, fmaxf(sf[ni][0], sf[ni][1]));
            mx1 = fmaxf(mx1, fmaxf(sf[ni][2], sf[ni][3]));
        }
        mx0 = fmaxf(mx0, __shfl_xor_sync(0xffffffffu, mx0, 1));
        mx0 = fmaxf(mx0, __shfl_xor_sync(0xffffffffu, mx0, 2));
        mx1 = fmaxf(mx1, __shfl_xor_sync(0xffffffffu, mx1, 1));
        mx1 = fmaxf(mx1, __shfl_xor_sync(0xffffffffu, mx1, 2));
        const float nm0 = fmaxf(m0, mx0), nm1 = fmaxf(m1, mx1);
        const float al0 = __expf(m0 - nm0), al1 = __expf(m1 - nm1);
        m0 = nm0; m1 = nm1;

        unsigned ph0[8], ph1[8];   // P as half2 A-fragments (rows gid / gid+8)
        float s0 = 0.f, s1 = 0.f;
#pragma unroll
        for (int ni = 0; ni < 8; ni++) {
            const float p0 = __expf(sf[ni][0] - m0);
            const float p1 = __expf(sf[ni][1] - m0);
            const float p2 = __expf(sf[ni][2] - m1);
            const float p3 = __expf(sf[ni][3] - m1);
            s0 += p0 + p1; s1 += p2 + p3;
            __half2 hh0 = __floats2half2_rn(p0, p1); ph0[ni] = *(unsigned*)&hh0;
            __half2 hh1 = __floats2half2_rn(p2, p3); ph1[ni] = *(unsigned*)&hh1;
        }
        s0 += __shfl_xor_sync(0xffffffffu, s0, 1);
        s0 += __shfl_xor_sync(0xffffffffu, s0, 2);
        s1 += __shfl_xor_sync(0xffffffffu, s1, 1);
        s1 += __shfl_xor_sync(0xffffffffu, s1, 2);
        l0 = l0 * al0 + s0;
        l1 = l1 * al1 + s1;

#pragma unroll
        for (int ni = 0; ni < 8; ni++) {
            oa[ni][0] *= al0; oa[ni][1] *= al0;
            oa[ni][2] *= al1; oa[ni][3] *= al1;
        }

        // --- O += P @ V : A = P (regs), B = V via ldmatrix.trans
#pragma unroll
        for (int s = 0; s < 4; s++) {          // k (kv) step of 16
            unsigned a[4] = {ph0[2 * s], ph1[2 * s],
                             ph0[2 * s + 1], ph1[2 * s + 1]};
#pragma unroll
            for (int nip = 0; nip < 4; nip++) { // d-tiles 2nip, 2nip+1
                unsigned r0, r1, r2, r3;
                ldsm_x4t(r0, r1, r2, r3,
                         &vbuf[(16 * s + (lane & 15)) * KP +
                               nip * 16 + (lane >> 4) * 8]);
                unsigned bb0[2] = {r0, r1}, bb1[2] = {r2, r3};
                mma16(oa[2 * nip],     a, bb0);
                mma16(oa[2 * nip + 1], a, bb1);
            }
        }

        if (t < S_LEN / 64 - 1) FILL_KV(buf ^ 1, (t + 1) * 64);
        __syncthreads();
    }
#undef FILL_KV

    // --- epilogue: normalize, write [b, q, h*64 + d] as fp16
    __half* ob = g_att + ((size_t)(b * S_LEN + q0)) * D_MODEL + h * HEAD_D;
    (void)O;
    const float li0 = 1.f / l0, li1 = 1.f / l1;
#pragma unroll
    for (int ni = 0; ni < 8; ni++) {
        const int c = 8 * ni + 2 * tig;
        *(__half2*)(ob + (size_t)(wm + gid) * D_MODEL + c) =
            __floats2half2_rn(oa[ni][0] * li0, oa[ni][1] * li0);
        *(__half2*)(ob + (size_t)(wm + gid + 8) * D_MODEL + c) =
            __floats2half2_rn(oa[ni][2] * li1, oa[ni][3] * li1);
    }
}

// ---------------------------------------------------------------------------
// Launch
// ---------------------------------------------------------------------------
extern "C" void kernel_launch(void* const* d_in, const int* in_sizes, int n_in,
                              void* d_out, int out_size) {
    const float* x  = (const float*)d_in[0];
    const float* Wq = (const float*)d_in[1];
    const float* bq = (const float*)d_in[2];
    const float* Wk = (const float*)d_in[3];
    const float* bk = (const float*)d_in[4];
    const float* Wv = (const float*)d_in[5];
    const float* bv = (const float*)d_in[6];
    const float* Wo = (const float*)d_in[7];
    const float* bo = (const float*)d_in[8];
    float* out = (float*)d_out;

    void *qp, *kp, *vp, *ap;
    cudaGetSymbolAddress(&qp, g_q);
    cudaGetSymbolAddress(&kp, g_k);
    cudaGetSymbolAddress(&vp, g_v);
    cudaGetSymbolAddress(&ap, g_att);

    const int ATT_SMEM = (128 * QP + 2 * 64 * KP + 2 * 64 * KP) * (int)sizeof(__half);
    cudaFuncSetAttribute(attn_f16,
                         cudaFuncAttributeMaxDynamicSharedMemorySize, ATT_SMEM);

    dim3 qkv_grid(D_MODEL / 128, M_ROWS / 128, 3);   // (6, 32, 3)
    qkv_gemm<<<qkv_grid, 256>>>(x, Wq, bq, Wk, bk, Wv, bv,
                                (__half*)qp, (__half*)kp, (__half*)vp);

    dim3 attn_grid(S_LEN / 128, N_HEADS, BATCH);     // (16, 12, 2)
    attn_f16<<<attn_grid, 256, ATT_SMEM>>>((const __half*)qp,
                                           (const __half*)kp,
                                           (const __half*)vp,
                                           (__half*)ap);

    dim3 o_grid(D_MODEL / 128, M_ROWS / 128);        // (6, 32)
    o_gemm<<<o_grid, 256>>>((const __half*)ap, Wo, bo, out);
}

// round 11
// speedup vs baseline: 7.8292x; 1.6929x over previous
#include <cuda_runtime.h>
#include <cuda_fp16.h>
#include <cstdint>

// Problem constants
#define BATCH   2
#define S_LEN   2048
#define D_MODEL 768
#define N_HEADS 12
#define HEAD_D  64
#define M_ROWS  (BATCH * S_LEN)   // 4096

// ---------------------------------------------------------------------------
// Scratch (no allocations allowed -> __device__ globals). fp16 everywhere.
// ---------------------------------------------------------------------------
__device__ __half g_q[M_ROWS * D_MODEL];
__device__ __half g_k[M_ROWS * D_MODEL];
__device__ __half g_v[M_ROWS * D_MODEL];
__device__ __half g_att[M_ROWS * D_MODEL];
__device__ __half g_xh[M_ROWS * D_MODEL];
__device__ __half g_wq[D_MODEL * D_MODEL];
__device__ __half g_wk[D_MODEL * D_MODEL];
__device__ __half g_wv[D_MODEL * D_MODEL];
__device__ __half g_wo[D_MODEL * D_MODEL];

// ---------------------------------------------------------------------------
// mma / ldmatrix / cp.async helpers
// ---------------------------------------------------------------------------
__device__ __forceinline__ void mma16(float c[4], const unsigned a[4],
                                      const unsigned b[2]) {
    asm volatile(
        "mma.sync.aligned.m16n8k16.row.col.f32.f16.f16.f32 "
        "{%0,%1,%2,%3}, {%4,%5,%6,%7}, {%8,%9}, {%0,%1,%2,%3};"
        : "+f"(c[0]), "+f"(c[1]), "+f"(c[2]), "+f"(c[3])
        : "r"(a[0]), "r"(a[1]), "r"(a[2]), "r"(a[3]),
          "r"(b[0]), "r"(b[1]));
}

__device__ __forceinline__ void ldsm_x4(unsigned& r0, unsigned& r1,
                                        unsigned& r2, unsigned& r3,
                                        const __half* p) {
    uint32_t a = (uint32_t)__cvta_generic_to_shared(p);
    asm volatile("ldmatrix.sync.aligned.m8n8.x4.shared.b16 {%0,%1,%2,%3}, [%4];"
                 : "=r"(r0), "=r"(r1), "=r"(r2), "=r"(r3) : "r"(a));
}

__device__ __forceinline__ void ldsm_x4t(unsigned& r0, unsigned& r1,
                                         unsigned& r2, unsigned& r3,
                                         const __half* p) {
    uint32_t a = (uint32_t)__cvta_generic_to_shared(p);
    asm volatile("ldmatrix.sync.aligned.m8n8.x4.trans.shared.b16 {%0,%1,%2,%3}, [%4];"
                 : "=r"(r0), "=r"(r1), "=r"(r2), "=r"(r3) : "r"(a));
}

__device__ __forceinline__ void cp_async16(__half* dst, const __half* src) {
    uint32_t d = (uint32_t)__cvta_generic_to_shared(dst);
    asm volatile("cp.async.cg.shared.global [%0], [%1], 16;" :: "r"(d), "l"(src));
}
#define CP_COMMIT() asm volatile("cp.async.commit_group;" ::: "memory")
template <int N>
__device__ __forceinline__ void cp_wait() {
    asm volatile("cp.async.wait_group %0;" :: "n"(N) : "memory");
}

__device__ __forceinline__ void st2(float* p, float a, float b) {
    *(float2*)p = make_float2(a, b);
}
__device__ __forceinline__ void st2(__half* p, float a, float b) {
    *(__half2*)p = __floats2half2_rn(a, b);
}

// ---------------------------------------------------------------------------
// One-shot fp32 -> fp16 conversion of x and the four weight matrices.
// 2048 elems per block (256 thr x 8). Segments: x = 1536 blocks, W = 288 each.
// ---------------------------------------------------------------------------
__global__ __launch_bounds__(256)
void cvt_all(const float* __restrict__ x,
             const float* __restrict__ wq, const float* __restrict__ wk,
             const float* __restrict__ wv, const float* __restrict__ wo) {
    const float* src; __half* dst; size_t off;
    const int bx = blockIdx.x;
    if (bx < 1536)      { src = x;  dst = g_xh; off = (size_t)bx * 2048; }
    else if (bx < 1824) { src = wq; dst = g_wq; off = (size_t)(bx - 1536) * 2048; }
    else if (bx < 2112) { src = wk; dst = g_wk; off = (size_t)(bx - 1824) * 2048; }
    else if (bx < 2400) { src = wv; dst = g_wv; off = (size_t)(bx - 2112) * 2048; }
    else                { src = wo; dst = g_wo; off = (size_t)(bx - 2400) * 2048; }
    off += (size_t)threadIdx.x * 8;
    float4 a = *(const float4*)(src + off);
    float4 b = *(const float4*)(src + off + 4);
    __half2* d = (__half2*)(dst + off);
    d[0] = __floats2half2_rn(a.x, a.y);
    d[1] = __floats2half2_rn(a.z, a.w);
    d[2] = __floats2half2_rn(b.x, b.y);
    d[3] = __floats2half2_rn(b.z, b.w);
}

// ---------------------------------------------------------------------------
// GEMM: C[4096,768] = A[4096,768] @ W[768,768] + bias (optionally * scale).
// Block 128x128, BK=32 (24 k-tiles), 8 warps (2x4), warp tile 64x32,
// fp16 mma m16n8k16. cp.async two-deep pipeline (fill t+1 issued BEFORE
// computing tile t -> global latency hidden under mma work).
// As pitch 40 halves (80B, 16B-mult), Ws pitch 136 halves (272B).
// ---------------------------------------------------------------------------
#define AP_G 40
#define WP_G 136
#define KTILES (D_MODEL / 32)   // 24

template <typename TOUT>
__device__ __forceinline__
void gemm_body(const __half* __restrict__ A, const __half* __restrict__ W,
               const float* __restrict__ bias, TOUT* __restrict__ C,
               float scale) {
    __shared__ __half As[2][128 * AP_G];
    __shared__ __half Ws[2][32 * WP_G];

    const int tid  = threadIdx.x;
    const int lane = tid & 31, wid = tid >> 5;
    const int gid  = lane >> 2, tig = lane & 3;
    const int wm   = (wid >> 2) * 64;
    const int wn   = (wid & 3) * 32;
    const int row0 = blockIdx.y * 128;
    const int col0 = blockIdx.x * 128;

    float acc[4][4][4];
#pragma unroll
    for (int mi = 0; mi < 4; mi++)
#pragma unroll
        for (int ni = 0; ni < 4; ni++)
#pragma unroll
            for (int j = 0; j < 4; j++) acc[mi][ni][j] = 0.f;

    // Async fill: A tile 128x32 halves = 512 x 16B chunks; W tile 32x128 same.
#define FILL_ASYNC(bf, k0)                                                     \
    {                                                                          \
        _Pragma("unroll")                                                      \
        for (int j = 0; j < 2; j++) {                                          \
            const int ch = tid + 256 * j;                                      \
            const int r = ch >> 2, c8 = (ch & 3) << 3;                         \
            cp_async16(&As[bf][r * AP_G + c8],                                 \
                       A + (size_t)(row0 + r) * D_MODEL + (k0) + c8);          \
        }                                                                      \
        _Pragma("unroll")                                                      \
        for (int j = 0; j < 2; j++) {                                          \
            const int ch = tid + 256 * j;                                      \
            const int r = ch >> 4, c8 = (ch & 15) << 3;                        \
            cp_async16(&Ws[bf][r * WP_G + c8],                                 \
                       W + (size_t)((k0) + r) * D_MODEL + col0 + c8);          \
        }                                                                      \
    }

    FILL_ASYNC(0, 0);
    CP_COMMIT();

    for (int t = 0; t < KTILES; t++) {
        const int buf = t & 1;
        if (t < KTILES - 1) {
            FILL_ASYNC(buf ^ 1, (t + 1) * 32);   // into free buffer
            CP_COMMIT();
            cp_wait<1>();                         // tile t resident
        } else {
            cp_wait<0>();
        }
        __syncthreads();

#pragma unroll
        for (int ks = 0; ks < 2; ks++) {
            const int kk = ks * 16;
            unsigned a[4][4];
#pragma unroll
            for (int mi = 0; mi < 4; mi++)
                ldsm_x4(a[mi][0], a[mi][1], a[mi][2], a[mi][3],
                        &As[buf][(wm + mi * 16 + (lane & 15)) * AP_G +
                                 kk + (lane >> 4) * 8]);
#pragma unroll
            for (int nip = 0; nip < 2; nip++) {
                unsigned r0, r1, r2, r3;
                ldsm_x4t(r0, r1, r2, r3,
                         &Ws[buf][(kk + (lane & 15)) * WP_G +
                                  wn + nip * 16 + (lane >> 4) * 8]);
                unsigned b0[2] = {r0, r1}, b1[2] = {r2, r3};
#pragma unroll
                for (int mi = 0; mi < 4; mi++) {
                    mma16(acc[mi][2 * nip],     a[mi], b0);
                    mma16(acc[mi][2 * nip + 1], a[mi], b1);
                }
            }
        }
        __syncthreads();   // protects buf from next iteration's fill
    }
#undef FILL_ASYNC

    // epilogue: (acc + bias) * scale, paired stores
#pragma unroll
    for (int mi = 0; mi < 4; mi++) {
        const int r = row0 + wm + mi * 16 + gid;
#pragma unroll
        for (int ni = 0; ni < 4; ni++) {
            const int c = col0 + wn + 8 * ni + 2 * tig;
            const float b0 = bias[c], b1 = bias[c + 1];
            st2(C + (size_t)r * D_MODEL + c,
                (acc[mi][ni][0] + b0) * scale, (acc[mi][ni][1] + b1) * scale);
            st2(C + (size_t)(r + 8) * D_MODEL + c,
                (acc[mi][ni][2] + b0) * scale, (acc[mi][ni][3] + b1) * scale);
        }
    }
}

// Fused QKV projection. Q output is pre-scaled by 1/sqrt(64) = 0.125 so the
// attention kernel can fill Q with raw cp.async (no multiply).
__global__ __launch_bounds__(256)
void qkv_gemm(const float* __restrict__ bq, const float* __restrict__ bk,
              const float* __restrict__ bv) {
    if (blockIdx.z == 0)
        gemm_body<__half>(g_xh, g_wq, bq, g_q, 0.125f);
    else if (blockIdx.z == 1)
        gemm_body<__half>(g_xh, g_wk, bk, g_k, 1.0f);
    else
        gemm_body<__half>(g_xh, g_wv, bv, g_v, 1.0f);
}

__global__ __launch_bounds__(256)
void o_gemm(const float* __restrict__ bias, float* __restrict__ out) {
    gemm_body<float>(g_att, g_wo, bias, out, 1.0f);
}

// ---------------------------------------------------------------------------
// Flash attention, fp16 mma, register-resident softmax (compute body is
// identical to the R9 passing kernel). Fills converted to cp.async with the
// same two-deep pipeline; Q arrives pre-scaled from qkv_gemm.
// ---------------------------------------------------------------------------
#define QP 72
#define KP 72

__global__ __launch_bounds__(256)
void attn_f16(const __half* __restrict__ Q, const __half* __restrict__ K,
              const __half* __restrict__ V, __half* __restrict__ O) {
    extern __shared__ __half sh[];
    __half* Qs = sh;                   // [128][QP]
    __half* Ks = Qs + 128 * QP;        // [2][64*KP]
    __half* Vs = Ks + 2 * 64 * KP;     // [2][64*KP]

    const int tid  = threadIdx.x;
    const int lane = tid & 31, wid = tid >> 5;
    const int gid  = lane >> 2, tig = lane & 3;
    const int wm   = wid * 16;
    const int b    = blockIdx.z, h = blockIdx.y;
    const int q0   = blockIdx.x * 128;

    const __half* qb = Q + ((size_t)(b * S_LEN + q0)) * D_MODEL + h * HEAD_D;
    const __half* kb = K + ((size_t)b * S_LEN) * D_MODEL + h * HEAD_D;
    const __half* vb = V + ((size_t)b * S_LEN) * D_MODEL + h * HEAD_D;

    // Q fill: 128x64 halves = 1024 x 16B chunks, 4 per thread (group 0)
#pragma unroll
    for (int j = 0; j < 4; j++) {
        const int ch = tid + 256 * j;
        const int r = ch >> 3, c8 = (ch & 7) << 3;
        cp_async16(&Qs[r * QP + c8], qb + (size_t)r * D_MODEL + c8);
    }

    // K+V fill for one kv-tile: 2 x 512 chunks, 2 per thread per array.
#define FILL_KV_ASYNC(bf, kt)                                                  \
    {                                                                          \
        __half* kd = &Ks[(bf) * 64 * KP];                                      \
        __half* vd = &Vs[(bf) * 64 * KP];                                      \
        _Pragma("unroll")                                                      \
        for (int j = 0; j < 2; j++) {                                          \
            const int ch = tid + 256 * j;                                      \
            const int r = ch >> 3, c8 = (ch & 7) << 3;                         \
            cp_async16(&kd[r * KP + c8],                                       \
                       kb + (size_t)((kt) + r) * D_MODEL + c8);                \
            cp_async16(&vd[r * KP + c8],                                       \
                       vb + (size_t)((kt) + r) * D_MODEL + c8);                \
        }                                                                      \
    }

    float m0 = -1e30f, m1 = -1e30f, l0 = 0.f, l1 = 0.f;
    float oa[8][4];
#pragma unroll
    for (int ni = 0; ni < 8; ni++)
#pragma unroll
        for (int j = 0; j < 4; j++) oa[ni][j] = 0.f;

    FILL_KV_ASYNC(0, 0);
    CP_COMMIT();   // group 0 = {Q, K0, V0}

    for (int t = 0; t < S_LEN / 64; ++t) {
        const int buf = t & 1;
        if (t < S_LEN / 64 - 1) {
            FILL_KV_ASYNC(buf ^ 1, (t + 1) * 64);
            CP_COMMIT();
            cp_wait<1>();
        } else {
            cp_wait<0>();
        }
        __syncthreads();

        const __half* kbuf = &Ks[buf * 64 * KP];
        const __half* vbuf = &Vs[buf * 64 * KP];

        // --- S = Q @ K^T : rows wm..wm+15, all 64 kv cols, accum fp32
        float sf[8][4];
#pragma unroll
        for (int ni = 0; ni < 8; ni++)
#pragma unroll
            for (int j = 0; j < 4; j++) sf[ni][j] = 0.f;

#pragma unroll
        for (int s = 0; s < 4; s++) {          // k (head-dim) step of 16
            unsigned a[4];
            ldsm_x4(a[0], a[1], a[2], a[3],
                    &Qs[(wm + (lane & 15)) * QP + 16 * s + (lane >> 4) * 8]);
#pragma unroll
            for (int nip = 0; nip < 4; nip++) { // kv-tiles 2nip, 2nip+1
                unsigned r0, r1, r2, r3;
                ldsm_x4(r0, r1, r2, r3,
                        &kbuf[(nip * 16 + (lane & 7) + ((lane >> 4) & 1) * 8) * KP +
                              16 * s + ((lane >> 3) & 1) * 8]);
                unsigned bb0[2] = {r0, r1}, bb1[2] = {r2, r3};
                mma16(sf[2 * nip],     a, bb0);
                mma16(sf[2 * nip + 1], a, bb1);
            }
        }

        // --- register-resident online softmax (rows gid and gid+8)
        float mx0 = sf[0][0], mx1 = sf[0][2];
#pragma unroll
        for (int ni = 0; ni < 8; ni++) {
            mx0 = fmaxf(mx0, fmaxf(sf[ni][0], sf[ni][1]));
            mx1 = fmaxf(mx1, fmaxf(sf[ni][2], sf[ni][3]));
        }
        mx0 = fmaxf(mx0, __shfl_xor_sync(0xffffffffu, mx0, 1));
        mx0 = fmaxf(mx0, __shfl_xor_sync(0xffffffffu, mx0, 2));
        mx1 = fmaxf(mx1, __shfl_xor_sync(0xffffffffu, mx1, 1));
        mx1 = fmaxf(mx1, __shfl_xor_sync(0xffffffffu, mx1, 2));
        const float nm0 = fmaxf(m0, mx0), nm1 = fmaxf(m1, mx1);
        const float al0 = __expf(m0 - nm0), al1 = __expf(m1 - nm1);
        m0 = nm0; m1 = nm1;

        unsigned ph0[8], ph1[8];   // P as half2 A-fragments (rows gid / gid+8)
        float s0 = 0.f, s1 = 0.f;
#pragma unroll
        for (int ni = 0; ni < 8; ni++) {
            const float p0 = __expf(sf[ni][0] - m0);
            const float p1 = __expf(sf[ni][1] - m0);
            const float p2 = __expf(sf[ni][2] - m1);
            const float p3 = __expf(sf[ni][3] - m1);
            s0 += p0 + p1; s1 += p2 + p3;
            __half2 hh0 = __floats2half2_rn(p0, p1); ph0[ni] = *(unsigned*)&hh0;
            __half2 hh1 = __floats2half2_rn(p2, p3); ph1[ni] = *(unsigned*)&hh1;
        }
        s0 += __shfl_xor_sync(0xffffffffu, s0, 1);
        s0 += __shfl_xor_sync(0xffffffffu, s0, 2);
        s1 += __shfl_xor_sync(0xffffffffu, s1, 1);
        s1 += __shfl_xor_sync(0xffffffffu, s1, 2);
        l0 = l0 * al0 + s0;
        l1 = l1 * al1 + s1;

#pragma unroll
        for (int ni = 0; ni < 8; ni++) {
            oa[ni][0] *= al0; oa[ni][1] *= al0;
            oa[ni][2] *= al1; oa[ni][3] *= al1;
        }

        // --- O += P @ V : A = P (regs), B = V via ldmatrix.trans
#pragma unroll
        for (int s = 0; s < 4; s++) {          // k (kv) step of 16
            unsigned a[4] = {ph0[2 * s], ph1[2 * s],
                             ph0[2 * s + 1], ph1[2 * s + 1]};
#pragma unroll
            for (int nip = 0; nip < 4; nip++) { // d-tiles 2nip, 2nip+1
                unsigned r0, r1, r2, r3;
                ldsm_x4t(r0, r1, r2, r3,
                         &vbuf[(16 * s + (lane & 15)) * KP +
                               nip * 16 + (lane >> 4) * 8]);
                unsigned bb0[2] = {r0, r1}, bb1[2] = {r2, r3};
                mma16(oa[2 * nip],     a, bb0);
                mma16(oa[2 * nip + 1], a, bb1);
            }
        }
        __syncthreads();   // protects buf from next iteration's fill
    }
#undef FILL_KV_ASYNC

    // --- epilogue: normalize, write [b, q, h*64 + d] as fp16
    __half* ob = O + ((size_t)(b * S_LEN + q0)) * D_MODEL + h * HEAD_D;
    const float li0 = 1.f / l0, li1 = 1.f / l1;
#pragma unroll
    for (int ni = 0; ni < 8; ni++) {
        const int c = 8 * ni + 2 * tig;
        *(__half2*)(ob + (size_t)(wm + gid) * D_MODEL + c) =
            __floats2half2_rn(oa[ni][0] * li0, oa[ni][1] * li0);
        *(__half2*)(ob + (size_t)(wm + gid + 8) * D_MODEL + c) =
            __floats2half2_rn(oa[ni][2] * li1, oa[ni][3] * li1);
    }
}

// ---------------------------------------------------------------------------
// Launch
// ---------------------------------------------------------------------------
extern "C" void kernel_launch(void* const* d_in, const int* in_sizes, int n_in,
                              void* d_out, int out_size) {
    const float* x  = (const float*)d_in[0];
    const float* Wq = (const float*)d_in[1];
    const float* bq = (const float*)d_in[2];
    const float* Wk = (const float*)d_in[3];
    const float* bk = (const float*)d_in[4];
    const float* Wv = (const float*)d_in[5];
    const float* bv = (const float*)d_in[6];
    const float* Wo = (const float*)d_in[7];
    const float* bo = (const float*)d_in[8];
    float* out = (float*)d_out;

    void *qp, *kp, *vp, *ap;
    cudaGetSymbolAddress(&qp, g_q);
    cudaGetSymbolAddress(&kp, g_k);
    cudaGetSymbolAddress(&vp, g_v);
    cudaGetSymbolAddress(&ap, g_att);

    const int ATT_SMEM = (128 * QP + 2 * 64 * KP + 2 * 64 * KP) * (int)sizeof(__half);
    cudaFuncSetAttribute(attn_f16,
                         cudaFuncAttributeMaxDynamicSharedMemorySize, ATT_SMEM);

    // fp32 -> fp16 conversion of x + all weights (2688 blocks)
    cvt_all<<<2688, 256>>>(x, Wq, Wk, Wv, Wo);

    dim3 qkv_grid(D_MODEL / 128, M_ROWS / 128, 3);   // (6, 32, 3)
    qkv_gemm<<<qkv_grid, 256>>>(bq, bk, bv);

    dim3 attn_grid(S_LEN / 128, N_HEADS, BATCH);     // (16, 12, 2)
    attn_f16<<<attn_grid, 256, ATT_SMEM>>>((const __half*)qp,
                                           (const __half*)kp,
                                           (const __half*)vp,
                                           (__half*)ap);

    dim3 o_grid(D_MODEL / 128, M_ROWS / 128);        // (6, 32)
    o_gemm<<<o_grid, 256>>>(bo, out);
}

// round 12
// speedup vs baseline: 8.0033x; 1.0222x over previous
#include <cuda_runtime.h>
#include <cuda_fp16.h>
#include <cstdint>

// Problem constants
#define BATCH   2
#define S_LEN   2048
#define D_MODEL 768
#define N_HEADS 12
#define HEAD_D  64
#define M_ROWS  (BATCH * S_LEN)   // 4096

// ---------------------------------------------------------------------------
// Scratch (no allocations allowed -> __device__ globals). fp16 everywhere.
// ---------------------------------------------------------------------------
__device__ __half g_q[M_ROWS * D_MODEL];
__device__ __half g_k[M_ROWS * D_MODEL];
__device__ __half g_v[M_ROWS * D_MODEL];
__device__ __half g_att[M_ROWS * D_MODEL];
__device__ __half g_xh[M_ROWS * D_MODEL];
__device__ __half g_wq[D_MODEL * D_MODEL];
__device__ __half g_wk[D_MODEL * D_MODEL];
__device__ __half g_wv[D_MODEL * D_MODEL];
__device__ __half g_wo[D_MODEL * D_MODEL];

// ---------------------------------------------------------------------------
// mma / ldmatrix / cp.async helpers
// ---------------------------------------------------------------------------
__device__ __forceinline__ void mma16(float c[4], const unsigned a[4],
                                      const unsigned b[2]) {
    asm volatile(
        "mma.sync.aligned.m16n8k16.row.col.f32.f16.f16.f32 "
        "{%0,%1,%2,%3}, {%4,%5,%6,%7}, {%8,%9}, {%0,%1,%2,%3};"
        : "+f"(c[0]), "+f"(c[1]), "+f"(c[2]), "+f"(c[3])
        : "r"(a[0]), "r"(a[1]), "r"(a[2]), "r"(a[3]),
          "r"(b[0]), "r"(b[1]));
}

__device__ __forceinline__ void ldsm_x4(unsigned& r0, unsigned& r1,
                                        unsigned& r2, unsigned& r3,
                                        const __half* p) {
    uint32_t a = (uint32_t)__cvta_generic_to_shared(p);
    asm volatile("ldmatrix.sync.aligned.m8n8.x4.shared.b16 {%0,%1,%2,%3}, [%4];"
                 : "=r"(r0), "=r"(r1), "=r"(r2), "=r"(r3) : "r"(a));
}

__device__ __forceinline__ void ldsm_x4t(unsigned& r0, unsigned& r1,
                                         unsigned& r2, unsigned& r3,
                                         const __half* p) {
    uint32_t a = (uint32_t)__cvta_generic_to_shared(p);
    asm volatile("ldmatrix.sync.aligned.m8n8.x4.trans.shared.b16 {%0,%1,%2,%3}, [%4];"
                 : "=r"(r0), "=r"(r1), "=r"(r2), "=r"(r3) : "r"(a));
}

__device__ __forceinline__ void cp_async16(__half* dst, const __half* src) {
    uint32_t d = (uint32_t)__cvta_generic_to_shared(dst);
    asm volatile("cp.async.cg.shared.global [%0], [%1], 16;" :: "r"(d), "l"(src));
}
#define CP_COMMIT() asm volatile("cp.async.commit_group;" ::: "memory")
template <int N>
__device__ __forceinline__ void cp_wait() {
    asm volatile("cp.async.wait_group %0;" :: "n"(N) : "memory");
}

__device__ __forceinline__ void st2(float* p, float a, float b) {
    *(float2*)p = make_float2(a, b);
}
__device__ __forceinline__ void st2(__half* p, float a, float b) {
    *(__half2*)p = __floats2half2_rn(a, b);
}

// ---------------------------------------------------------------------------
// One-shot fp32 -> fp16 conversion of x and the four weight matrices.
// ---------------------------------------------------------------------------
__global__ __launch_bounds__(256)
void cvt_all(const float* __restrict__ x,
             const float* __restrict__ wq, const float* __restrict__ wk,
             const float* __restrict__ wv, const float* __restrict__ wo) {
    const float* src; __half* dst; size_t off;
    const int bx = blockIdx.x;
    if (bx < 1536)      { src = x;  dst = g_xh; off = (size_t)bx * 2048; }
    else if (bx < 1824) { src = wq; dst = g_wq; off = (size_t)(bx - 1536) * 2048; }
    else if (bx < 2112) { src = wk; dst = g_wk; off = (size_t)(bx - 1824) * 2048; }
    else if (bx < 2400) { src = wv; dst = g_wv; off = (size_t)(bx - 2112) * 2048; }
    else                { src = wo; dst = g_wo; off = (size_t)(bx - 2400) * 2048; }
    off += (size_t)threadIdx.x * 8;
    float4 a = *(const float4*)(src + off);
    float4 b = *(const float4*)(src + off + 4);
    __half2* d = (__half2*)(dst + off);
    d[0] = __floats2half2_rn(a.x, a.y);
    d[1] = __floats2half2_rn(a.z, a.w);
    d[2] = __floats2half2_rn(b.x, b.y);
    d[3] = __floats2half2_rn(b.z, b.w);
}

// ---------------------------------------------------------------------------
// GEMM: C[4096,768] = A[4096,768] @ W[768,768] + bias (optionally * scale).
// Block 128x128, BK=64 (12 k-tiles), 8 warps (2x4), warp tile 64x32.
// 2-stage cp.async pipeline, ONE __syncthreads per k-tile:
//   iter t: wait_group 0 -> sync -> issue fill t+1 -> compute t
// (fill t+1 overwrites the stage last read at t-1; the sync proves all warps
//  are past that read). Dynamic smem: 2*(128*72 + 64*136)*2 = 71680 B.
// As pitch 72 halves (144B): ldmatrix bank-quad = r*9 mod 8 = r mod 8 (ok).
// Ws pitch 136 halves (272B): bank-quad = r*17 mod 8 = r mod 8 (ok).
// ---------------------------------------------------------------------------
#define AP_G 72
#define WP_G 136
#define KTILES (D_MODEL / 64)   // 12
#define GEMM_SMEM ((2 * 128 * AP_G + 2 * 64 * WP_G) * (int)sizeof(__half))

template <typename TOUT>
__device__ __forceinline__
void gemm_body(const __half* __restrict__ A, const __half* __restrict__ W,
               const float* __restrict__ bias, TOUT* __restrict__ C,
               float scale) {
    extern __shared__ __half dynsm[];
    __half* As = dynsm;                 // [2][128*AP_G]
    __half* Ws = dynsm + 2 * 128 * AP_G;// [2][64*WP_G]

    const int tid  = threadIdx.x;
    const int lane = tid & 31, wid = tid >> 5;
    const int gid  = lane >> 2, tig = lane & 3;
    const int wm   = (wid >> 2) * 64;
    const int wn   = (wid & 3) * 32;
    const int row0 = blockIdx.y * 128;
    const int col0 = blockIdx.x * 128;

    float acc[4][4][4];
#pragma unroll
    for (int mi = 0; mi < 4; mi++)
#pragma unroll
        for (int ni = 0; ni < 4; ni++)
#pragma unroll
            for (int j = 0; j < 4; j++) acc[mi][ni][j] = 0.f;

    // A tile 128x64 halves = 1024 16B chunks; W tile 64x128 = 1024 chunks.
#define FILL_ASYNC(bf, k0)                                                     \
    {                                                                          \
        __half* ad = As + (bf) * 128 * AP_G;                                   \
        __half* wd = Ws + (bf) * 64 * WP_G;                                    \
        _Pragma("unroll")                                                      \
        for (int j = 0; j < 4; j++) {                                          \
            const int ch = tid + 256 * j;                                      \
            const int r = ch >> 3, c8 = (ch & 7) << 3;                         \
            cp_async16(&ad[r * AP_G + c8],                                     \
                       A + (size_t)(row0 + r) * D_MODEL + (k0) + c8);          \
        }                                                                      \
        _Pragma("unroll")                                                      \
        for (int j = 0; j < 4; j++) {                                          \
            const int ch = tid + 256 * j;                                      \
            const int r = ch >> 4, c8 = (ch & 15) << 3;                        \
            cp_async16(&wd[r * WP_G + c8],                                     \
                       W + (size_t)((k0) + r) * D_MODEL + col0 + c8);          \
        }                                                                      \
    }

    FILL_ASYNC(0, 0);
    CP_COMMIT();

    for (int t = 0; t < KTILES; t++) {
        const int buf = t & 1;
        cp_wait<0>();
        __syncthreads();
        if (t < KTILES - 1) {
            FILL_ASYNC(buf ^ 1, (t + 1) * 64);
            CP_COMMIT();
        }
        const __half* ab = As + buf * 128 * AP_G;
        const __half* wb = Ws + buf * 64 * WP_G;

#pragma unroll
        for (int ks = 0; ks < 4; ks++) {
            const int kk = ks * 16;
            unsigned a[4][4];
#pragma unroll
            for (int mi = 0; mi < 4; mi++)
                ldsm_x4(a[mi][0], a[mi][1], a[mi][2], a[mi][3],
                        &ab[(wm + mi * 16 + (lane & 15)) * AP_G +
                            kk + (lane >> 4) * 8]);
#pragma unroll
            for (int nip = 0; nip < 2; nip++) {
                unsigned r0, r1, r2, r3;
                ldsm_x4t(r0, r1, r2, r3,
                         &wb[(kk + (lane & 15)) * WP_G +
                             wn + nip * 16 + (lane >> 4) * 8]);
                unsigned b0[2] = {r0, r1}, b1[2] = {r2, r3};
#pragma unroll
                for (int mi = 0; mi < 4; mi++) {
                    mma16(acc[mi][2 * nip],     a[mi], b0);
                    mma16(acc[mi][2 * nip + 1], a[mi], b1);
                }
            }
        }
    }
#undef FILL_ASYNC

    // epilogue: (acc + bias) * scale, paired stores
#pragma unroll
    for (int mi = 0; mi < 4; mi++) {
        const int r = row0 + wm + mi * 16 + gid;
#pragma unroll
        for (int ni = 0; ni < 4; ni++) {
            const int c = col0 + wn + 8 * ni + 2 * tig;
            const float b0 = bias[c], b1 = bias[c + 1];
            st2(C + (size_t)r * D_MODEL + c,
                (acc[mi][ni][0] + b0) * scale, (acc[mi][ni][1] + b1) * scale);
            st2(C + (size_t)(r + 8) * D_MODEL + c,
                (acc[mi][ni][2] + b0) * scale, (acc[mi][ni][3] + b1) * scale);
        }
    }
}

// Fused QKV projection. Q output pre-scaled by 1/sqrt(64) = 0.125.
__global__ __launch_bounds__(256)
void qkv_gemm(const float* __restrict__ bq, const float* __restrict__ bk,
              const float* __restrict__ bv) {
    if (blockIdx.z == 0)
        gemm_body<__half>(g_xh, g_wq, bq, g_q, 0.125f);
    else if (blockIdx.z == 1)
        gemm_body<__half>(g_xh, g_wk, bk, g_k, 1.0f);
    else
        gemm_body<__half>(g_xh, g_wv, bv, g_v, 1.0f);
}

__global__ __launch_bounds__(256)
void o_gemm(const float* __restrict__ bias, float* __restrict__ out) {
    gemm_body<float>(g_att, g_wo, bias, out, 1.0f);
}

// ---------------------------------------------------------------------------
// Flash attention, fp16 mma, register-resident softmax. Same single-sync
// 2-stage pipeline: iter t: wait 0 -> sync -> issue KV fill t+1 -> compute t.
// ---------------------------------------------------------------------------
#define QP 72
#define KP 72

__global__ __launch_bounds__(256)
void attn_f16(const __half* __restrict__ Q, const __half* __restrict__ K,
              const __half* __restrict__ V, __half* __restrict__ O) {
    extern __shared__ __half sh[];
    __half* Qs = sh;                   // [128][QP]
    __half* Ks = Qs + 128 * QP;        // [2][64*KP]
    __half* Vs = Ks + 2 * 64 * KP;     // [2][64*KP]

    const int tid  = threadIdx.x;
    const int lane = tid & 31, wid = tid >> 5;
    const int gid  = lane >> 2, tig = lane & 3;
    const int wm   = wid * 16;
    const int b    = blockIdx.z, h = blockIdx.y;
    const int q0   = blockIdx.x * 128;

    const __half* qb = Q + ((size_t)(b * S_LEN + q0)) * D_MODEL + h * HEAD_D;
    const __half* kb = K + ((size_t)b * S_LEN) * D_MODEL + h * HEAD_D;
    const __half* vb = V + ((size_t)b * S_LEN) * D_MODEL + h * HEAD_D;

    // Q fill: 128x64 halves = 1024 x 16B chunks
#pragma unroll
    for (int j = 0; j < 4; j++) {
        const int ch = tid + 256 * j;
        const int r = ch >> 3, c8 = (ch & 7) << 3;
        cp_async16(&Qs[r * QP + c8], qb + (size_t)r * D_MODEL + c8);
    }

#define FILL_KV_ASYNC(bf, kt)                                                  \
    {                                                                          \
        __half* kd = &Ks[(bf) * 64 * KP];                                      \
        __half* vd = &Vs[(bf) * 64 * KP];                                      \
        _Pragma("unroll")                                                      \
        for (int j = 0; j < 2; j++) {                                          \
            const int ch = tid + 256 * j;                                      \
            const int r = ch >> 3, c8 = (ch & 7) << 3;                         \
            cp_async16(&kd[r * KP + c8],                                       \
                       kb + (size_t)((kt) + r) * D_MODEL + c8);                \
            cp_async16(&vd[r * KP + c8],                                       \
                       vb + (size_t)((kt) + r) * D_MODEL + c8);                \
        }                                                                      \
    }

    float m0 = -1e30f, m1 = -1e30f, l0 = 0.f, l1 = 0.f;
    float oa[8][4];
#pragma unroll
    for (int ni = 0; ni < 8; ni++)
#pragma unroll
        for (int j = 0; j < 4; j++) oa[ni][j] = 0.f;

    FILL_KV_ASYNC(0, 0);
    CP_COMMIT();

    for (int t = 0; t < S_LEN / 64; ++t) {
        const int buf = t & 1;
        cp_wait<0>();
        __syncthreads();
        if (t < S_LEN / 64 - 1) {
            FILL_KV_ASYNC(buf ^ 1, (t + 1) * 64);
            CP_COMMIT();
        }

        const __half* kbuf = &Ks[buf * 64 * KP];
        const __half* vbuf = &Vs[buf * 64 * KP];

        // --- S = Q @ K^T : rows wm..wm+15, all 64 kv cols, accum fp32
        float sf[8][4];
#pragma unroll
        for (int ni = 0; ni < 8; ni++)
#pragma unroll
            for (int j = 0; j < 4; j++) sf[ni][j] = 0.f;

#pragma unroll
        for (int s = 0; s < 4; s++) {          // k (head-dim) step of 16
            unsigned a[4];
            ldsm_x4(a[0], a[1], a[2], a[3],
                    &Qs[(wm + (lane & 15)) * QP + 16 * s + (lane >> 4) * 8]);
#pragma unroll
            for (int nip = 0; nip < 4; nip++) { // kv-tiles 2nip, 2nip+1
                unsigned r0, r1, r2, r3;
                ldsm_x4(r0, r1, r2, r3,
                        &kbuf[(nip * 16 + (lane & 7) + ((lane >> 4) & 1) * 8) * KP +
                              16 * s + ((lane >> 3) & 1) * 8]);
                unsigned bb0[2] = {r0, r1}, bb1[2] = {r2, r3};
                mma16(sf[2 * nip],     a, bb0);
                mma16(sf[2 * nip + 1], a, bb1);
            }
        }

        // --- register-resident online softmax (rows gid and gid+8)
        float mx0 = sf[0][0], mx1 = sf[0][2];
#pragma unroll
        for (int ni = 0; ni < 8; ni++) {
            mx0 = fmaxf(mx0, fmaxf(sf[ni][0], sf[ni][1]));
            mx1 = fmaxf(mx1, fmaxf(sf[ni][2], sf[ni][3]));
        }
        mx0 = fmaxf(mx0, __shfl_xor_sync(0xffffffffu, mx0, 1));
        mx0 = fmaxf(mx0, __shfl_xor_sync(0xffffffffu, mx0, 2));
        mx1 = fmaxf(mx1, __shfl_xor_sync(0xffffffffu, mx1, 1));
        mx1 = fmaxf(mx1, __shfl_xor_sync(0xffffffffu, mx1, 2));
        const float nm0 = fmaxf(m0, mx0), nm1 = fmaxf(m1, mx1);
        const float al0 = __expf(m0 - nm0), al1 = __expf(m1 - nm1);
        m0 = nm0; m1 = nm1;

        unsigned ph0[8], ph1[8];   // P as half2 A-fragments (rows gid / gid+8)
        float s0 = 0.f, s1 = 0.f;
#pragma unroll
        for (int ni = 0; ni < 8; ni++) {
            const float p0 = __expf(sf[ni][0] - m0);
            const float p1 = __expf(sf[ni][1] - m0);
            const float p2 = __expf(sf[ni][2] - m1);
            const float p3 = __expf(sf[ni][3] - m1);
            s0 += p0 + p1; s1 += p2 + p3;
            __half2 hh0 = __floats2half2_rn(p0, p1); ph0[ni] = *(unsigned*)&hh0;
            __half2 hh1 = __floats2half2_rn(p2, p3); ph1[ni] = *(unsigned*)&hh1;
        }
        s0 += __shfl_xor_sync(0xffffffffu, s0, 1);
        s0 += __shfl_xor_sync(0xffffffffu, s0, 2);
        s1 += __shfl_xor_sync(0xffffffffu, s1, 1);
        s1 += __shfl_xor_sync(0xffffffffu, s1, 2);
        l0 = l0 * al0 + s0;
        l1 = l1 * al1 + s1;

#pragma unroll
        for (int ni = 0; ni < 8; ni++) {
            oa[ni][0] *= al0; oa[ni][1] *= al0;
            oa[ni][2] *= al1; oa[ni][3] *= al1;
        }

        // --- O += P @ V : A = P (regs), B = V via ldmatrix.trans
#pragma unroll
        for (int s = 0; s < 4; s++) {          // k (kv) step of 16
            unsigned a[4] = {ph0[2 * s], ph1[2 * s],
                             ph0[2 * s + 1], ph1[2 * s + 1]};
#pragma unroll
            for (int nip = 0; nip < 4; nip++) { // d-tiles 2nip, 2nip+1
                unsigned r0, r1, r2, r3;
                ldsm_x4t(r0, r1, r2, r3,
                         &vbuf[(16 * s + (lane & 15)) * KP +
                               nip * 16 + (lane >> 4) * 8]);
                unsigned bb0[2] = {r0, r1}, bb1[2] = {r2, r3};
                mma16(oa[2 * nip],     a, bb0);
                mma16(oa[2 * nip + 1], a, bb1);
            }
        }
    }
#undef FILL_KV_ASYNC

    // --- epilogue: normalize, write [b, q, h*64 + d] as fp16
    __half* ob = O + ((size_t)(b * S_LEN + q0)) * D_MODEL + h * HEAD_D;
    const float li0 = 1.f / l0, li1 = 1.f / l1;
#pragma unroll
    for (int ni = 0; ni < 8; ni++) {
        const int c = 8 * ni + 2 * tig;
        *(__half2*)(ob + (size_t)(wm + gid) * D_MODEL + c) =
            __floats2half2_rn(oa[ni][0] * li0, oa[ni][1] * li0);
        *(__half2*)(ob + (size_t)(wm + gid + 8) * D_MODEL + c) =
            __floats2half2_rn(oa[ni][2] * li1, oa[ni][3] * li1);
    }
}

// ---------------------------------------------------------------------------
// Launch
// ---------------------------------------------------------------------------
extern "C" void kernel_launch(void* const* d_in, const int* in_sizes, int n_in,
                              void* d_out, int out_size) {
    const float* x  = (const float*)d_in[0];
    const float* Wq = (const float*)d_in[1];
    const float* bq = (const float*)d_in[2];
    const float* Wk = (const float*)d_in[3];
    const float* bk = (const float*)d_in[4];
    const float* Wv = (const float*)d_in[5];
    const float* bv = (const float*)d_in[6];
    const float* Wo = (const float*)d_in[7];
    const float* bo = (const float*)d_in[8];
    float* out = (float*)d_out;

    void *qp, *kp, *vp, *ap;
    cudaGetSymbolAddress(&qp, g_q);
    cudaGetSymbolAddress(&kp, g_k);
    cudaGetSymbolAddress(&vp, g_v);
    cudaGetSymbolAddress(&ap, g_att);

    const int ATT_SMEM = (128 * QP + 2 * 64 * KP + 2 * 64 * KP) * (int)sizeof(__half);
    cudaFuncSetAttribute(attn_f16,
                         cudaFuncAttributeMaxDynamicSharedMemorySize, ATT_SMEM);
    cudaFuncSetAttribute(qkv_gemm,
                         cudaFuncAttributeMaxDynamicSharedMemorySize, GEMM_SMEM);
    cudaFuncSetAttribute(o_gemm,
                         cudaFuncAttributeMaxDynamicSharedMemorySize, GEMM_SMEM);

    // fp32 -> fp16 conversion of x + all weights (2688 blocks)
    cvt_all<<<2688, 256>>>(x, Wq, Wk, Wv, Wo);

    dim3 qkv_grid(D_MODEL / 128, M_ROWS / 128, 3);   // (6, 32, 3)
    qkv_gemm<<<qkv_grid, 256, GEMM_SMEM>>>(bq, bk, bv);

    dim3 attn_grid(S_LEN / 128, N_HEADS, BATCH);     // (16, 12, 2)
    attn_f16<<<attn_grid, 256, ATT_SMEM>>>((const __half*)qp,
                                           (const __half*)kp,
                                           (const __half*)vp,
                                           (__half*)ap);

    dim3 o_grid(D_MODEL / 128, M_ROWS / 128);        // (6, 32)
    o_gemm<<<o_grid, 256, GEMM_SMEM>>>(bo, out);
}

// round 13
// speedup vs baseline: 8.1910x; 1.0235x over previous
#include <cuda_runtime.h>
#include <cuda_fp16.h>
#include <cstdint>

// Problem constants
#define BATCH   2
#define S_LEN   2048
#define D_MODEL 768
#define N_HEADS 12
#define HEAD_D  64
#define M_ROWS  (BATCH * S_LEN)   // 4096

// ---------------------------------------------------------------------------
// Scratch (no allocations allowed -> __device__ globals). fp16 everywhere.
// ---------------------------------------------------------------------------
__device__ __half g_q[M_ROWS * D_MODEL];
__device__ __half g_k[M_ROWS * D_MODEL];
__device__ __half g_v[M_ROWS * D_MODEL];
__device__ __half g_att[M_ROWS * D_MODEL];
__device__ __half g_xh[M_ROWS * D_MODEL];
__device__ __half g_wq[D_MODEL * D_MODEL];
__device__ __half g_wk[D_MODEL * D_MODEL];
__device__ __half g_wv[D_MODEL * D_MODEL];
__device__ __half g_wo[D_MODEL * D_MODEL];

// ---------------------------------------------------------------------------
// mma / ldmatrix / cp.async helpers
// ---------------------------------------------------------------------------
__device__ __forceinline__ void mma16(float c[4], const unsigned a[4],
                                      const unsigned b[2]) {
    asm volatile(
        "mma.sync.aligned.m16n8k16.row.col.f32.f16.f16.f32 "
        "{%0,%1,%2,%3}, {%4,%5,%6,%7}, {%8,%9}, {%0,%1,%2,%3};"
        : "+f"(c[0]), "+f"(c[1]), "+f"(c[2]), "+f"(c[3])
        : "r"(a[0]), "r"(a[1]), "r"(a[2]), "r"(a[3]),
          "r"(b[0]), "r"(b[1]));
}

__device__ __forceinline__ void ldsm_x4(unsigned& r0, unsigned& r1,
                                        unsigned& r2, unsigned& r3,
                                        const __half* p) {
    uint32_t a = (uint32_t)__cvta_generic_to_shared(p);
    asm volatile("ldmatrix.sync.aligned.m8n8.x4.shared.b16 {%0,%1,%2,%3}, [%4];"
                 : "=r"(r0), "=r"(r1), "=r"(r2), "=r"(r3) : "r"(a));
}

__device__ __forceinline__ void ldsm_x4t(unsigned& r0, unsigned& r1,
                                         unsigned& r2, unsigned& r3,
                                         const __half* p) {
    uint32_t a = (uint32_t)__cvta_generic_to_shared(p);
    asm volatile("ldmatrix.sync.aligned.m8n8.x4.trans.shared.b16 {%0,%1,%2,%3}, [%4];"
                 : "=r"(r0), "=r"(r1), "=r"(r2), "=r"(r3) : "r"(a));
}

__device__ __forceinline__ void cp_async16(__half* dst, const __half* src) {
    uint32_t d = (uint32_t)__cvta_generic_to_shared(dst);
    asm volatile("cp.async.cg.shared.global [%0], [%1], 16;" :: "r"(d), "l"(src));
}
#define CP_COMMIT() asm volatile("cp.async.commit_group;" ::: "memory")
template <int N>
__device__ __forceinline__ void cp_wait() {
    asm volatile("cp.async.wait_group %0;" :: "n"(N) : "memory");
}

// one MUFU for two fp16 exp2's
__device__ __forceinline__ unsigned ex2_f16x2(unsigned x) {
    unsigned r;
    asm("ex2.approx.f16x2 %0, %1;" : "=r"(r) : "r"(x));
    return r;
}

__device__ __forceinline__ void st2(float* p, float a, float b) {
    *(float2*)p = make_float2(a, b);
}
__device__ __forceinline__ void st2(__half* p, float a, float b) {
    *(__half2*)p = __floats2half2_rn(a, b);
}

// ---------------------------------------------------------------------------
// One-shot fp32 -> fp16 conversion of x and the four weight matrices.
// ---------------------------------------------------------------------------
__global__ __launch_bounds__(256)
void cvt_all(const float* __restrict__ x,
             const float* __restrict__ wq, const float* __restrict__ wk,
             const float* __restrict__ wv, const float* __restrict__ wo) {
    const float* src; __half* dst; size_t off;
    const int bx = blockIdx.x;
    if (bx < 1536)      { src = x;  dst = g_xh; off = (size_t)bx * 2048; }
    else if (bx < 1824) { src = wq; dst = g_wq; off = (size_t)(bx - 1536) * 2048; }
    else if (bx < 2112) { src = wk; dst = g_wk; off = (size_t)(bx - 1824) * 2048; }
    else if (bx < 2400) { src = wv; dst = g_wv; off = (size_t)(bx - 2112) * 2048; }
    else                { src = wo; dst = g_wo; off = (size_t)(bx - 2400) * 2048; }
    off += (size_t)threadIdx.x * 8;
    float4 a = *(const float4*)(src + off);
    float4 b = *(const float4*)(src + off + 4);
    __half2* d = (__half2*)(dst + off);
    d[0] = __floats2half2_rn(a.x, a.y);
    d[1] = __floats2half2_rn(a.z, a.w);
    d[2] = __floats2half2_rn(b.x, b.y);
    d[3] = __floats2half2_rn(b.z, b.w);
}

// ---------------------------------------------------------------------------
// GEMM: C[4096,768] = A[4096,768] @ W[768,768] + bias (optionally * scale).
// Block 256x128, 512 threads, 16 warps (4m x 4n), warp tile 64x32 (unchanged
// per-warp code). BK=64 (12 k-tiles), 2-stage cp.async, one sync per tile.
// Every active SM now carries 16 warps (4/SMSP); o_gemm grid = 96 -> single
// clean wave on 148 SMs.
// Dynamic smem: 2*256*72 + 2*64*136 halves = 108544 B -> 1 CTA/SM (reg-bound
// anyway: ~95 regs x 512 thr).
// ---------------------------------------------------------------------------
#define AP_G 72
#define WP_G 136
#define KTILES (D_MODEL / 64)   // 12
#define GEMM_SMEM ((2 * 256 * AP_G + 2 * 64 * WP_G) * (int)sizeof(__half))

template <typename TOUT>
__device__ __forceinline__
void gemm_body(const __half* __restrict__ A, const __half* __restrict__ W,
               const float* __restrict__ bias, TOUT* __restrict__ C,
               float scale) {
    extern __shared__ __half dynsm[];
    __half* As = dynsm;                  // [2][256*AP_G]
    __half* Ws = dynsm + 2 * 256 * AP_G; // [2][64*WP_G]

    const int tid  = threadIdx.x;
    const int lane = tid & 31, wid = tid >> 5;
    const int gid  = lane >> 2, tig = lane & 3;
    const int wm   = (wid >> 2) * 64;    // 0..192
    const int wn   = (wid & 3) * 32;     // 0..96
    const int row0 = blockIdx.y * 256;
    const int col0 = blockIdx.x * 128;

    float acc[4][4][4];
#pragma unroll
    for (int mi = 0; mi < 4; mi++)
#pragma unroll
        for (int ni = 0; ni < 4; ni++)
#pragma unroll
            for (int j = 0; j < 4; j++) acc[mi][ni][j] = 0.f;

    // A tile 256x64 halves = 2048 16B chunks (4/thread);
    // W tile 64x128 = 1024 chunks (2/thread).
#define FILL_ASYNC(bf, k0)                                                     \
    {                                                                          \
        __half* ad = As + (bf) * 256 * AP_G;                                   \
        __half* wd = Ws + (bf) * 64 * WP_G;                                    \
        _Pragma("unroll")                                                      \
        for (int j = 0; j < 4; j++) {                                          \
            const int ch = tid + 512 * j;                                      \
            const int r = ch >> 3, c8 = (ch & 7) << 3;                         \
            cp_async16(&ad[r * AP_G + c8],                                     \
                       A + (size_t)(row0 + r) * D_MODEL + (k0) + c8);          \
        }                                                                      \
        _Pragma("unroll")                                                      \
        for (int j = 0; j < 2; j++) {                                          \
            const int ch = tid + 512 * j;                                      \
            const int r = ch >> 4, c8 = (ch & 15) << 3;                        \
            cp_async16(&wd[r * WP_G + c8],                                     \
                       W + (size_t)((k0) + r) * D_MODEL + col0 + c8);          \
        }                                                                      \
    }

    FILL_ASYNC(0, 0);
    CP_COMMIT();

    for (int t = 0; t < KTILES; t++) {
        const int buf = t & 1;
        cp_wait<0>();
        __syncthreads();
        if (t < KTILES - 1) {
            FILL_ASYNC(buf ^ 1, (t + 1) * 64);
            CP_COMMIT();
        }
        const __half* ab = As + buf * 256 * AP_G;
        const __half* wb = Ws + buf * 64 * WP_G;

#pragma unroll
        for (int ks = 0; ks < 4; ks++) {
            const int kk = ks * 16;
            unsigned a[4][4];
#pragma unroll
            for (int mi = 0; mi < 4; mi++)
                ldsm_x4(a[mi][0], a[mi][1], a[mi][2], a[mi][3],
                        &ab[(wm + mi * 16 + (lane & 15)) * AP_G +
                            kk + (lane >> 4) * 8]);
#pragma unroll
            for (int nip = 0; nip < 2; nip++) {
                unsigned r0, r1, r2, r3;
                ldsm_x4t(r0, r1, r2, r3,
                         &wb[(kk + (lane & 15)) * WP_G +
                             wn + nip * 16 + (lane >> 4) * 8]);
                unsigned b0[2] = {r0, r1}, b1[2] = {r2, r3};
#pragma unroll
                for (int mi = 0; mi < 4; mi++) {
                    mma16(acc[mi][2 * nip],     a[mi], b0);
                    mma16(acc[mi][2 * nip + 1], a[mi], b1);
                }
            }
        }
    }
#undef FILL_ASYNC

    // epilogue: (acc + bias) * scale, paired stores
#pragma unroll
    for (int mi = 0; mi < 4; mi++) {
        const int r = row0 + wm + mi * 16 + gid;
#pragma unroll
        for (int ni = 0; ni < 4; ni++) {
            const int c = col0 + wn + 8 * ni + 2 * tig;
            const float b0 = bias[c], b1 = bias[c + 1];
            st2(C + (size_t)r * D_MODEL + c,
                (acc[mi][ni][0] + b0) * scale, (acc[mi][ni][1] + b1) * scale);
            st2(C + (size_t)(r + 8) * D_MODEL + c,
                (acc[mi][ni][2] + b0) * scale, (acc[mi][ni][3] + b1) * scale);
        }
    }
}

// Fused QKV projection. Q output pre-scaled by 1/sqrt(64) = 0.125.
__global__ __launch_bounds__(512)
void qkv_gemm(const float* __restrict__ bq, const float* __restrict__ bk,
              const float* __restrict__ bv) {
    if (blockIdx.z == 0)
        gemm_body<__half>(g_xh, g_wq, bq, g_q, 0.125f);
    else if (blockIdx.z == 1)
        gemm_body<__half>(g_xh, g_wk, bk, g_k, 1.0f);
    else
        gemm_body<__half>(g_xh, g_wv, bv, g_v, 1.0f);
}

__global__ __launch_bounds__(512)
void o_gemm(const float* __restrict__ bias, float* __restrict__ out) {
    gemm_body<float>(g_att, g_wo, bias, out, 1.0f);
}

// ---------------------------------------------------------------------------
// Flash attention, fp16 mma, register-resident softmax.
// exp via ex2.approx.f16x2: one MUFU per TWO P-values, result is directly the
// packed half2 mma A-fragment. Row sums stay fp32 (denominator precision).
// 2-stage cp.async, one __syncthreads per kv-tile (wait+sync at loop bottom).
// ---------------------------------------------------------------------------
#define QP 72
#define KP 72

__global__ __launch_bounds__(256)
void attn_f16(const __half* __restrict__ Q, const __half* __restrict__ K,
              const __half* __restrict__ V, __half* __restrict__ O) {
    extern __shared__ __half sh[];
    __half* Qs = sh;                   // [128][QP]
    __half* Ks = Qs + 128 * QP;        // [2][64*KP]
    __half* Vs = Ks + 2 * 64 * KP;     // [2][64*KP]

    const int tid  = threadIdx.x;
    const int lane = tid & 31, wid = tid >> 5;
    const int gid  = lane >> 2, tig = lane & 3;
    const int wm   = wid * 16;
    const int b    = blockIdx.z, h = blockIdx.y;
    const int q0   = blockIdx.x * 128;

    const __half* qb = Q + ((size_t)(b * S_LEN + q0)) * D_MODEL + h * HEAD_D;
    const __half* kb = K + ((size_t)b * S_LEN) * D_MODEL + h * HEAD_D;
    const __half* vb = V + ((size_t)b * S_LEN) * D_MODEL + h * HEAD_D;

    // Q fill: 128x64 halves = 1024 x 16B chunks
#pragma unroll
    for (int j = 0; j < 4; j++) {
        const int ch = tid + 256 * j;
        const int r = ch >> 3, c8 = (ch & 7) << 3;
        cp_async16(&Qs[r * QP + c8], qb + (size_t)r * D_MODEL + c8);
    }

#define FILL_KV_ASYNC(bf, kt)                                                  \
    {                                                                          \
        __half* kd = &Ks[(bf) * 64 * KP];                                      \
        __half* vd = &Vs[(bf) * 64 * KP];                                      \
        _Pragma("unroll")                                                      \
        for (int j = 0; j < 2; j++) {                                          \
            const int ch = tid + 256 * j;                                      \
            const int r = ch >> 3, c8 = (ch & 7) << 3;                         \
            cp_async16(&kd[r * KP + c8],                                       \
                       kb + (size_t)((kt) + r) * D_MODEL + c8);                \
            cp_async16(&vd[r * KP + c8],                                       \
                       vb + (size_t)((kt) + r) * D_MODEL + c8);                \
        }                                                                      \
    }

    float m0 = -1e30f, m1 = -1e30f, l0 = 0.f, l1 = 0.f;
    float oa[8][4];
#pragma unroll
    for (int ni = 0; ni < 8; ni++)
#pragma unroll
        for (int j = 0; j < 4; j++) oa[ni][j] = 0.f;

    FILL_KV_ASYNC(0, 0);
    CP_COMMIT();
    cp_wait<0>();
    __syncthreads();

    for (int t = 0; t < S_LEN / 64; ++t) {
        const int buf = t & 1;
        if (t < S_LEN / 64 - 1) {
            FILL_KV_ASYNC(buf ^ 1, (t + 1) * 64);  // overwrites tile read at t-1
            CP_COMMIT();
        }

        const __half* kbuf = &Ks[buf * 64 * KP];
        const __half* vbuf = &Vs[buf * 64 * KP];

        // --- S = Q @ K^T : rows wm..wm+15, all 64 kv cols, accum fp32
        float sf[8][4];
#pragma unroll
        for (int ni = 0; ni < 8; ni++)
#pragma unroll
            for (int j = 0; j < 4; j++) sf[ni][j] = 0.f;

#pragma unroll
        for (int s = 0; s < 4; s++) {          // k (head-dim) step of 16
            unsigned a[4];
            ldsm_x4(a[0], a[1], a[2], a[3],
                    &Qs[(wm + (lane & 15)) * QP + 16 * s + (lane >> 4) * 8]);
#pragma unroll
            for (int nip = 0; nip < 4; nip++) { // kv-tiles 2nip, 2nip+1
                unsigned r0, r1, r2, r3;
                ldsm_x4(r0, r1, r2, r3,
                        &kbuf[(nip * 16 + (lane & 7) + ((lane >> 4) & 1) * 8) * KP +
                              16 * s + ((lane >> 3) & 1) * 8]);
                unsigned bb0[2] = {r0, r1}, bb1[2] = {r2, r3};
                mma16(sf[2 * nip],     a, bb0);
                mma16(sf[2 * nip + 1], a, bb1);
            }
        }

        // --- register-resident online softmax (rows gid and gid+8)
        float mx0 = sf[0][0], mx1 = sf[0][2];
#pragma unroll
        for (int ni = 0; ni < 8; ni++) {
            mx0 = fmaxf(mx0, fmaxf(sf[ni][0], sf[ni][1]));
            mx1 = fmaxf(mx1, fmaxf(sf[ni][2], sf[ni][3]));
        }
        mx0 = fmaxf(mx0, __shfl_xor_sync(0xffffffffu, mx0, 1));
        mx0 = fmaxf(mx0, __shfl_xor_sync(0xffffffffu, mx0, 2));
        mx1 = fmaxf(mx1, __shfl_xor_sync(0xffffffffu, mx1, 1));
        mx1 = fmaxf(mx1, __shfl_xor_sync(0xffffffffu, mx1, 2));
        const float nm0 = fmaxf(m0, mx0), nm1 = fmaxf(m1, mx1);
        const float al0 = __expf(m0 - nm0), al1 = __expf(m1 - nm1);
        m0 = nm0; m1 = nm1;

        // exp(s - m) = exp2(s*log2e - m*log2e), two at a time on MUFU.
        const float L2E = 1.44269504f;
        const float base0 = m0 * L2E, base1 = m1 * L2E;
        unsigned ph0[8], ph1[8];   // P as half2 A-fragments (rows gid / gid+8)
        float s0 = 0.f, s1 = 0.f;
#pragma unroll
        for (int ni = 0; ni < 8; ni++) {
            __half2 a0 = __floats2half2_rn(fmaf(sf[ni][0], L2E, -base0),
                                           fmaf(sf[ni][1], L2E, -base0));
            __half2 a1 = __floats2half2_rn(fmaf(sf[ni][2], L2E, -base1),
                                           fmaf(sf[ni][3], L2E, -base1));
            ph0[ni] = ex2_f16x2(*(unsigned*)&a0);
            ph1[ni] = ex2_f16x2(*(unsigned*)&a1);
            float2 f0 = __half22float2(*(__half2*)&ph0[ni]);
            float2 f1 = __half22float2(*(__half2*)&ph1[ni]);
            s0 += f0.x + f0.y;
            s1 += f1.x + f1.y;
        }
        s0 += __shfl_xor_sync(0xffffffffu, s0, 1);
        s0 += __shfl_xor_sync(0xffffffffu, s0, 2);
        s1 += __shfl_xor_sync(0xffffffffu, s1, 1);
        s1 += __shfl_xor_sync(0xffffffffu, s1, 2);
        l0 = l0 * al0 + s0;
        l1 = l1 * al1 + s1;

#pragma unroll
        for (int ni = 0; ni < 8; ni++) {
            oa[ni][0] *= al0; oa[ni][1] *= al0;
            oa[ni][2] *= al1; oa[ni][3] *= al1;
        }

        // --- O += P @ V : A = P (regs), B = V via ldmatrix.trans
#pragma unroll
        for (int s = 0; s < 4; s++) {          // k (kv) step of 16
            unsigned a[4] = {ph0[2 * s], ph1[2 * s],
                             ph0[2 * s + 1], ph1[2 * s + 1]};
#pragma unroll
            for (int nip = 0; nip < 4; nip++) { // d-tiles 2nip, 2nip+1
                unsigned r0, r1, r2, r3;
                ldsm_x4t(r0, r1, r2, r3,
                         &vbuf[(16 * s + (lane & 15)) * KP +
                               nip * 16 + (lane >> 4) * 8]);
                unsigned bb0[2] = {r0, r1}, bb1[2] = {r2, r3};
                mma16(oa[2 * nip],     a, bb0);
                mma16(oa[2 * nip + 1], a, bb1);
            }
        }

        if (t < S_LEN / 64 - 1) {
            cp_wait<0>();        // next tile resident
            __syncthreads();     // all reads of current buffers done
        }
    }
#undef FILL_KV_ASYNC

    // --- epilogue: normalize, write [b, q, h*64 + d] as fp16
    __half* ob = O + ((size_t)(b * S_LEN + q0)) * D_MODEL + h * HEAD_D;
    const float li0 = 1.f / l0, li1 = 1.f / l1;
#pragma unroll
    for (int ni = 0; ni < 8; ni++) {
        const int c = 8 * ni + 2 * tig;
        *(__half2*)(ob + (size_t)(wm + gid) * D_MODEL + c) =
            __floats2half2_rn(oa[ni][0] * li0, oa[ni][1] * li0);
        *(__half2*)(ob + (size_t)(wm + gid + 8) * D_MODEL + c) =
            __floats2half2_rn(oa[ni][2] * li1, oa[ni][3] * li1);
    }
}

// ---------------------------------------------------------------------------
// Launch
// ---------------------------------------------------------------------------
extern "C" void kernel_launch(void* const* d_in, const int* in_sizes, int n_in,
                              void* d_out, int out_size) {
    const float* x  = (const float*)d_in[0];
    const float* Wq = (const float*)d_in[1];
    const float* bq = (const float*)d_in[2];
    const float* Wk = (const float*)d_in[3];
    const float* bk = (const float*)d_in[4];
    const float* Wv = (const float*)d_in[5];
    const float* bv = (const float*)d_in[6];
    const float* Wo = (const float*)d_in[7];
    const float* bo = (const float*)d_in[8];
    float* out = (float*)d_out;

    void *qp, *kp, *vp, *ap;
    cudaGetSymbolAddress(&qp, g_q);
    cudaGetSymbolAddress(&kp, g_k);
    cudaGetSymbolAddress(&vp, g_v);
    cudaGetSymbolAddress(&ap, g_att);

    const int ATT_SMEM = (128 * QP + 2 * 64 * KP + 2 * 64 * KP) * (int)sizeof(__half);
    cudaFuncSetAttribute(attn_f16,
                         cudaFuncAttributeMaxDynamicSharedMemorySize, ATT_SMEM);
    cudaFuncSetAttribute(qkv_gemm,
                         cudaFuncAttributeMaxDynamicSharedMemorySize, GEMM_SMEM);
    cudaFuncSetAttribute(o_gemm,
                         cudaFuncAttributeMaxDynamicSharedMemorySize, GEMM_SMEM);

    // fp32 -> fp16 conversion of x + all weights (2688 blocks)
    cvt_all<<<2688, 256>>>(x, Wq, Wk, Wv, Wo);

    dim3 qkv_grid(D_MODEL / 128, M_ROWS / 256, 3);   // (6, 16, 3) = 288
    qkv_gemm<<<qkv_grid, 512, GEMM_SMEM>>>(bq, bk, bv);

    dim3 attn_grid(S_LEN / 128, N_HEADS, BATCH);     // (16, 12, 2) = 384
    attn_f16<<<attn_grid, 256, ATT_SMEM>>>((const __half*)qp,
                                           (const __half*)kp,
                                           (const __half*)vp,
                                           (__half*)ap);

    dim3 o_grid(D_MODEL / 128, M_ROWS / 256);        // (6, 16) = 96
    o_gemm<<<o_grid, 512, GEMM_SMEM>>>(bo, out);
}